// round 8
// baseline (speedup 1.0000x reference)
#include <cuda_runtime.h>
#include <cuda_fp16.h>
#include <cstdint>

// ---------------- problem constants ----------------
#define SQ   2048
#define NB   2
#define NH   16
#define BH   (NB * NH)             // 32
#define HD   128
#define ROWSTRIDE (BH * HD)        // 4096 floats
#define MASK_ELEMS (NB * SQ * SQ)  // 8388608
#define MROWB (SQ / 8)             // 256 bytes per packed mask row

// ---------------- tiling ----------------
#define BM        128
#define BN        64
#define NTHREADS  256
#define PITCH     136              // half elems per smem row (272B), conflict-free ldmatrix
#define PITCHB    272
#define KVITERS   (SQ / BN)        // 32
#define NBUF      4

#define SCALE  0.08838834764831845f       // 1/sqrt(128)
#define LOG2E  1.4426950408889634f
#define SCL2   (SCALE * LOG2E)            // folded into Q in prepass

// smem: Q | (K0 V0)(K1 V1)(K2 V2)(K3 V3)
#define OFF_Q   0
#define TILE    17408              // 64 * 272
#define OFF_KV  34816
#define SMEM_BYTES (OFF_KV + NBUF * 2 * TILE)   // 174080

// ---------------- global scratch ----------------
__device__ __half   g_qh[(size_t)BH * SQ * HD];   // Q prescaled by SCL2
__device__ __half   g_kh[(size_t)BH * SQ * HD];
__device__ __half   g_vh[(size_t)BH * SQ * HD];
__device__ uint32_t g_mp[MASK_ELEMS / 32];        // packed mask bits
__device__ int      g_flags[2];

__global__ void reset_flags_kernel() { g_flags[0] = 0; g_flags[1] = 0; }

#define DETECT_WORDS (MASK_ELEMS / 4)
__global__ void detect_kernel(const uint32_t* __restrict__ m) {
    int f_f32 = 0, f_u8 = 0;
    for (int i = blockIdx.x * blockDim.x + threadIdx.x; i < DETECT_WORDS;
         i += gridDim.x * blockDim.x) {
        uint32_t w = m[i];
        if (w == 0x3F800000u) f_f32 = 1;
        else if (w > 1u)      f_u8  = 1;
    }
    if (f_f32) atomicOr(&g_flags[0], 1);
    if (f_u8)  atomicOr(&g_flags[1], 1);
}

__global__ void pack_mask_kernel(const void* __restrict__ m) {
    const int u8mode = (!g_flags[0] && g_flags[1]);
    const int NW = MASK_ELEMS / 32;
    for (int w = blockIdx.x * blockDim.x + threadIdx.x; w < NW;
         w += gridDim.x * blockDim.x) {
        uint32_t bits = 0;
        if (u8mode) {
            const uint8_t* p = (const uint8_t*)m + (size_t)w * 32;
            #pragma unroll
            for (int j = 0; j < 32; j++) bits |= (uint32_t)(p[j] != 0) << j;
        } else {
            const uint32_t* p = (const uint32_t*)m + (size_t)w * 32;
            #pragma unroll
            for (int j = 0; j < 32; j++) bits |= (uint32_t)(p[j] != 0u) << j;
        }
        g_mp[w] = bits;
    }
}

// fp32 [s][b][h][d] -> fp16 [bh][s][d]; Q additionally scaled by SCL2
__global__ void cvt_qkv_kernel(const float* __restrict__ Q, const float* __restrict__ K,
                               const float* __restrict__ V) {
    const int TOT = 3 * SQ * BH * (HD / 4);
    for (int i = blockIdx.x * blockDim.x + threadIdx.x; i < TOT;
         i += gridDim.x * blockDim.x) {
        int t  = i / (SQ * BH * (HD / 4));
        int r  = i - t * (SQ * BH * (HD / 4));
        int s  = r / (BH * (HD / 4));
        int r2 = r - s * (BH * (HD / 4));
        int bh = r2 >> 5;
        int c  = (r2 & 31) << 2;
        const float* src = (t == 0) ? Q : (t == 1) ? K : V;
        __half*      dst = (t == 0) ? g_qh : (t == 1) ? g_kh : g_vh;
        float4 v = *(const float4*)(src + (size_t)s * ROWSTRIDE + bh * HD + c);
        if (t == 0) { v.x *= SCL2; v.y *= SCL2; v.z *= SCL2; v.w *= SCL2; }
        __half2 h0 = __floats2half2_rn(v.x, v.y);
        __half2 h1 = __floats2half2_rn(v.z, v.w);
        uint2 u; u.x = *(uint32_t*)&h0; u.y = *(uint32_t*)&h1;
        *(uint2*)(dst + ((size_t)bh * SQ + s) * HD + c) = u;
    }
}

// ---------------- helpers ----------------
__device__ __forceinline__ uint32_t smem_u32(const void* p) {
    return (uint32_t)__cvta_generic_to_shared(p);
}
__device__ __forceinline__ void cp_async16(uint32_t dst, const void* src) {
    asm volatile("cp.async.cg.shared.global [%0], [%1], 16;" :: "r"(dst), "l"(src));
}
__device__ __forceinline__ void cp_commit() { asm volatile("cp.async.commit_group;"); }
template <int N> __device__ __forceinline__ void cp_wait() {
    asm volatile("cp.async.wait_group %0;" :: "n"(N));
}
__device__ __forceinline__ float ex2(float x) {
    float y; asm("ex2.approx.ftz.f32 %0, %1;" : "=f"(y) : "f"(x)); return y;
}
__device__ __forceinline__ void ldm_x4(uint32_t& r0, uint32_t& r1, uint32_t& r2, uint32_t& r3, uint32_t a) {
    asm volatile("ldmatrix.sync.aligned.m8n8.x4.shared.b16 {%0,%1,%2,%3}, [%4];"
                 : "=r"(r0), "=r"(r1), "=r"(r2), "=r"(r3) : "r"(a));
}
__device__ __forceinline__ void ldm_x4_t(uint32_t& r0, uint32_t& r1, uint32_t& r2, uint32_t& r3, uint32_t a) {
    asm volatile("ldmatrix.sync.aligned.m8n8.x4.trans.shared.b16 {%0,%1,%2,%3}, [%4];"
                 : "=r"(r0), "=r"(r1), "=r"(r2), "=r"(r3) : "r"(a));
}
__device__ __forceinline__ void mma16816(float* c, const uint32_t* a, uint32_t b0, uint32_t b1) {
    asm volatile("mma.sync.aligned.m16n8k16.row.col.f32.f16.f16.f32 "
                 "{%0,%1,%2,%3}, {%4,%5,%6,%7}, {%8,%9}, {%0,%1,%2,%3};"
                 : "+f"(c[0]), "+f"(c[1]), "+f"(c[2]), "+f"(c[3])
                 : "r"(a[0]), "r"(a[1]), "r"(a[2]), "r"(a[3]), "r"(b0), "r"(b1));
}
__device__ __forceinline__ uint32_t packh2(float x, float y) {
    __half2 h = __floats2half2_rn(x, y);
    return *(uint32_t*)&h;
}

// stage K,V tile t into buffer t%NBUF
__device__ __forceinline__ void stage_tiles(int tid, int kb, const __half* Kh, const __half* Vh,
                                            char* smem, int buf) {
    char* sKs = smem + OFF_KV + buf * 2 * TILE;
    char* sVs = sKs + TILE;
    #pragma unroll
    for (int j = 0; j < 4; j++) {
        int i = tid + j * NTHREADS;          // 0..1023
        int r = i >> 4, ck = i & 15;
        size_t so = (size_t)(kb + r) * HD + ck * 8;
        cp_async16(smem_u32(sKs + r * PITCHB + ck * 16), Kh + so);
        cp_async16(smem_u32(sVs + r * PITCHB + ck * 16), Vh + so);
    }
}

__global__ void __launch_bounds__(NTHREADS, 1)
attn_fwd_kernel(float* __restrict__ Og) {
    extern __shared__ char smem[];
    __half* sQ = (__half*)(smem + OFF_Q);

    const int tid  = threadIdx.x;
    const int lane = tid & 31;
    const int warp = tid >> 5;

    const int q0 = blockIdx.x * BM;
    const int bh = blockIdx.y;
    const int bb = bh >> 4;
    const __half* Qh = g_qh + (size_t)bh * SQ * HD;
    const __half* Kh = g_kh + (size_t)bh * SQ * HD;
    const __half* Vh = g_vh + (size_t)bh * SQ * HD;

    // ---- prologue staging: Q + tile0 (group 0), tile1 (group 1) ----
    #pragma unroll
    for (int j = 0; j < 8; j++) {
        int i = tid + j * NTHREADS;
        int r = i >> 4, ck = i & 15;
        cp_async16(smem_u32((char*)sQ + r * PITCHB + ck * 16),
                   Qh + (size_t)(q0 + r) * HD + ck * 8);
    }
    stage_tiles(tid, 0, Kh, Vh, smem, 0);
    cp_commit();
    stage_tiles(tid, BN, Kh, Vh, smem, 1);
    cp_commit();

    const int g  = lane >> 2;
    const int tg = lane & 3;
    const int m0 = warp * 16;

    const int arow = m0 + (lane & 7) + ((lane >> 3) & 1) * 8;
    const int acol = (lane >> 4) * 8;
    const int krow = (lane & 7) + ((lane >> 4) & 1) * 8;
    const int kcol = ((lane >> 3) & 1) * 8;
    const int vrow = (lane & 7) + ((lane >> 3) & 1) * 8;
    const int vcol = (lane >> 4) * 8;

    const uint8_t* mrow0 = (const uint8_t*)g_mp
                         + ((size_t)bb * SQ + q0 + m0 + g) * MROWB;
    const uint8_t* mrow1 = mrow0 + (size_t)8 * MROWB;
    const int msh = 2 * tg;

    float o[16][4];
    #pragma unroll
    for (int t = 0; t < 16; t++) { o[t][0]=0.f; o[t][1]=0.f; o[t][2]=0.f; o[t][3]=0.f; }
    float l0a = 0.f, l0b = 0.f, l1a = 0.f, l1b = 0.f;

    // wait Q + tile0, then resident Q fragments
    cp_wait<1>();
    __syncthreads();
    uint32_t aq[8][4];
    #pragma unroll
    for (int kt = 0; kt < 8; kt++) {
        ldm_x4(aq[kt][0], aq[kt][1], aq[kt][2], aq[kt][3],
               smem_u32(sQ + arow * PITCH + kt * 16 + acol));
    }

    // mask prefetch for tile 0
    uint2 nm0 = *(const uint2*)(mrow0);
    uint2 nm1 = *(const uint2*)(mrow1);

    float c4[8][4];
    #pragma unroll
    for (int t = 0; t < 8; t++) { c4[t][0]=0.f; c4[t][1]=0.f; c4[t][2]=0.f; c4[t][3]=0.f; }

    // ---- QK(0) ----
    {
        __half* sK0 = (__half*)(smem + OFF_KV);   // buf 0
        #pragma unroll
        for (int kt = 0; kt < 8; kt++) {
            #pragma unroll
            for (int n16 = 0; n16 < 4; n16++) {
                uint32_t b0, b1, b2, b3;
                ldm_x4(b0, b1, b2, b3,
                       smem_u32(sK0 + (n16 * 16 + krow) * PITCH + kt * 16 + kcol));
                mma16816(c4[2 * n16],     aq[kt], b0, b1);
                mma16816(c4[2 * n16 + 1], aq[kt], b2, b3);
            }
        }
    }

    // ---- main loop: body it does sm(it), then QK(it+1) interleaved with PV(it) ----
    for (int it = 0; it < KVITERS - 1; it++) {
        // stage tile it+2 (buffer (it+2)%4: last read in body it-2, safe)
        if (it + 2 < KVITERS) {
            stage_tiles(tid, (it + 2) * BN, Kh, Vh, smem, (it + 2) % NBUF);
        }
        cp_commit();
        cp_wait<1>();      // tile it+1 arrived
        __syncthreads();   // visibility + WAR separation

        __half* sVs = (__half*)(smem + OFF_KV + (it % NBUF) * 2 * TILE + TILE);
        __half* sKn = (__half*)(smem + OFF_KV + ((it + 1) % NBUF) * 2 * TILE);

        // rotate mask, prefetch next
        uint32_t wa0 = nm0.x >> msh, wb0 = nm0.y >> msh;
        uint32_t wa1 = nm1.x >> msh, wb1 = nm1.y >> msh;
        nm0 = *(const uint2*)(mrow0 + (it + 1) * 8);
        nm1 = *(const uint2*)(mrow1 + (it + 1) * 8);

        // ---- softmax(it): c4 -> pf ----
        uint32_t pf[4][4];
        #pragma unroll
        for (int nt = 0; nt < 8; nt++) {
            uint32_t ba  = (nt < 4) ? (wa0 >> (8 * nt)) : (wb0 >> (8 * (nt - 4)));
            uint32_t bb_ = (nt < 4) ? (wa1 >> (8 * nt)) : (wb1 >> (8 * (nt - 4)));
            float x0 = (ba  & 1u) ? -200.f : c4[nt][0];
            float x1 = (ba  & 2u) ? -200.f : c4[nt][1];
            float x2 = (bb_ & 1u) ? -200.f : c4[nt][2];
            float x3 = (bb_ & 2u) ? -200.f : c4[nt][3];
            float p0 = ex2(x0), p1 = ex2(x1), p2 = ex2(x2), p3 = ex2(x3);
            l0a += p0; l0b += p1;
            l1a += p2; l1b += p3;
            pf[nt >> 1][(nt & 1) * 2]     = packh2(p0, p1);
            pf[nt >> 1][(nt & 1) * 2 + 1] = packh2(p2, p3);
        }

        // zero c4 for QK(it+1)
        #pragma unroll
        for (int t = 0; t < 8; t++) { c4[t][0]=0.f; c4[t][1]=0.f; c4[t][2]=0.f; c4[t][3]=0.f; }

        // ---- interleaved: QK(it+1)  ||  PV(it) ----
        #pragma unroll
        for (int p = 0; p < 4; p++) {
            #pragma unroll
            for (int kk = 0; kk < 2; kk++) {
                int kt = 2 * p + kk;
                #pragma unroll
                for (int n16 = 0; n16 < 4; n16++) {
                    uint32_t b0, b1, b2, b3;
                    ldm_x4(b0, b1, b2, b3,
                           smem_u32(sKn + (n16 * 16 + krow) * PITCH + kt * 16 + kcol));
                    mma16816(c4[2 * n16],     aq[kt], b0, b1);
                    mma16816(c4[2 * n16 + 1], aq[kt], b2, b3);
                }
            }
            #pragma unroll
            for (int dn = 0; dn < 8; dn++) {
                uint32_t v0, v1, v2, v3;
                ldm_x4_t(v0, v1, v2, v3,
                         smem_u32(sVs + (p * 16 + vrow) * PITCH + dn * 16 + vcol));
                mma16816(o[2 * dn],     pf[p], v0, v1);
                mma16816(o[2 * dn + 1], pf[p], v2, v3);
            }
        }
    }

    // ---- tail: softmax + PV for last tile ----
    {
        const int it = KVITERS - 1;
        __half* sVs = (__half*)(smem + OFF_KV + (it % NBUF) * 2 * TILE + TILE);
        uint32_t wa0 = nm0.x >> msh, wb0 = nm0.y >> msh;
        uint32_t wa1 = nm1.x >> msh, wb1 = nm1.y >> msh;

        uint32_t pf[4][4];
        #pragma unroll
        for (int nt = 0; nt < 8; nt++) {
            uint32_t ba  = (nt < 4) ? (wa0 >> (8 * nt)) : (wb0 >> (8 * (nt - 4)));
            uint32_t bb_ = (nt < 4) ? (wa1 >> (8 * nt)) : (wb1 >> (8 * (nt - 4)));
            float x0 = (ba  & 1u) ? -200.f : c4[nt][0];
            float x1 = (ba  & 2u) ? -200.f : c4[nt][1];
            float x2 = (bb_ & 1u) ? -200.f : c4[nt][2];
            float x3 = (bb_ & 2u) ? -200.f : c4[nt][3];
            float p0 = ex2(x0), p1 = ex2(x1), p2 = ex2(x2), p3 = ex2(x3);
            l0a += p0; l0b += p1;
            l1a += p2; l1b += p3;
            pf[nt >> 1][(nt & 1) * 2]     = packh2(p0, p1);
            pf[nt >> 1][(nt & 1) * 2 + 1] = packh2(p2, p3);
        }
        #pragma unroll
        for (int p = 0; p < 4; p++) {
            #pragma unroll
            for (int dn = 0; dn < 8; dn++) {
                uint32_t v0, v1, v2, v3;
                ldm_x4_t(v0, v1, v2, v3,
                         smem_u32(sVs + (p * 16 + vrow) * PITCH + dn * 16 + vcol));
                mma16816(o[2 * dn],     pf[p], v0, v1);
                mma16816(o[2 * dn + 1], pf[p], v2, v3);
            }
        }
    }

    // ---- epilogue: quad-reduce l, normalize, store ----
    float l0 = l0a + l0b;
    float l1 = l1a + l1b;
    l0 += __shfl_xor_sync(0xffffffffu, l0, 1);
    l0 += __shfl_xor_sync(0xffffffffu, l0, 2);
    l1 += __shfl_xor_sync(0xffffffffu, l1, 1);
    l1 += __shfl_xor_sync(0xffffffffu, l1, 2);
    float i0 = 1.f / l0;
    float i1 = 1.f / l1;

    float* orow0 = Og + (size_t)(q0 + m0 + g) * ROWSTRIDE + bh * HD;
    float* orow1 = orow0 + (size_t)8 * ROWSTRIDE;
    #pragma unroll
    for (int nt = 0; nt < 16; nt++) {
        float2 v0, v1;
        v0.x = o[nt][0] * i0; v0.y = o[nt][1] * i0;
        v1.x = o[nt][2] * i1; v1.y = o[nt][3] * i1;
        *(float2*)(orow0 + nt * 8 + 2 * tg) = v0;
        *(float2*)(orow1 + nt * 8 + 2 * tg) = v1;
    }
}

extern "C" void kernel_launch(void* const* d_in, const int* in_sizes, int n_in,
                              void* d_out, int out_size) {
    const float* Q = (const float*)d_in[0];
    const float* K = (const float*)d_in[1];
    const float* V = (const float*)d_in[2];
    const void*  M = d_in[3];
    float*       O = (float*)d_out;

    reset_flags_kernel<<<1, 1>>>();
    detect_kernel<<<512, 256>>>((const uint32_t*)M);
    pack_mask_kernel<<<1024, 256>>>(M);
    cvt_qkv_kernel<<<8192, 256>>>(Q, K, V);

    cudaFuncSetAttribute(attn_fwd_kernel, cudaFuncAttributeMaxDynamicSharedMemorySize, SMEM_BYTES);
    dim3 grid(SQ / BM, BH);
    attn_fwd_kernel<<<grid, NTHREADS, SMEM_BYTES>>>(O);
}

// round 10
// speedup vs baseline: 1.4330x; 1.4330x over previous
#include <cuda_runtime.h>
#include <cuda_fp16.h>
#include <cstdint>

// ---------------- problem constants ----------------
#define SQ   2048
#define NB   2
#define NH   16
#define BH   (NB * NH)             // 32
#define HD   128
#define ROWSTRIDE (BH * HD)        // 4096 floats
#define MASK_ELEMS (NB * SQ * SQ)  // 8388608
#define MROWB (SQ / 8)             // 256 bytes per packed mask row

// ---------------- tiling ----------------
#define BM        128
#define BN        64
#define NTHREADS  256
#define PITCH     136              // half elems per smem row (272B), conflict-free ldmatrix
#define PITCHB    272
#define KVITERS   (SQ / BN)        // 32

#define SCALE  0.08838834764831845f       // 1/sqrt(128)
#define LOG2E  1.4426950408889634f
#define SCL2   (SCALE * LOG2E)            // folded into Q in prepass

// smem: Q | K0 V0 K1 V1 K2 V2  (triple-buffered KV)
#define OFF_Q   0
#define TILE    17408              // 64 * 272
#define OFF_K0  34816
#define OFF_V0  (OFF_K0 + TILE)
#define OFF_K1  (OFF_V0 + TILE)
#define OFF_V1  (OFF_K1 + TILE)
#define OFF_K2  (OFF_V1 + TILE)
#define OFF_V2  (OFF_K2 + TILE)
#define SMEM_BYTES (OFF_V2 + TILE)   // 139264

// ---------------- global scratch ----------------
__device__ __half   g_qh[(size_t)BH * SQ * HD];   // Q prescaled by SCL2
__device__ __half   g_kh[(size_t)BH * SQ * HD];
__device__ __half   g_vh[(size_t)BH * SQ * HD];
__device__ uint32_t g_mp[MASK_ELEMS / 32];        // packed mask bits
__device__ int      g_flags[2];

__global__ void reset_flags_kernel() { g_flags[0] = 0; g_flags[1] = 0; }

#define DETECT_WORDS (MASK_ELEMS / 4)
__global__ void detect_kernel(const uint32_t* __restrict__ m) {
    int f_f32 = 0, f_u8 = 0;
    for (int i = blockIdx.x * blockDim.x + threadIdx.x; i < DETECT_WORDS;
         i += gridDim.x * blockDim.x) {
        uint32_t w = m[i];
        if (w == 0x3F800000u) f_f32 = 1;
        else if (w > 1u)      f_u8  = 1;
    }
    if (f_f32) atomicOr(&g_flags[0], 1);
    if (f_u8)  atomicOr(&g_flags[1], 1);
}

__global__ void pack_mask_kernel(const void* __restrict__ m) {
    const int u8mode = (!g_flags[0] && g_flags[1]);
    const int NW = MASK_ELEMS / 32;
    for (int w = blockIdx.x * blockDim.x + threadIdx.x; w < NW;
         w += gridDim.x * blockDim.x) {
        uint32_t bits = 0;
        if (u8mode) {
            const uint8_t* p = (const uint8_t*)m + (size_t)w * 32;
            #pragma unroll
            for (int j = 0; j < 32; j++) bits |= (uint32_t)(p[j] != 0) << j;
        } else {
            const uint32_t* p = (const uint32_t*)m + (size_t)w * 32;
            #pragma unroll
            for (int j = 0; j < 32; j++) bits |= (uint32_t)(p[j] != 0u) << j;
        }
        g_mp[w] = bits;
    }
}

// fp32 [s][b][h][d] -> fp16 [bh][s][d]; Q additionally scaled by SCL2
__global__ void cvt_qkv_kernel(const float* __restrict__ Q, const float* __restrict__ K,
                               const float* __restrict__ V) {
    const int TOT = 3 * SQ * BH * (HD / 4);
    for (int i = blockIdx.x * blockDim.x + threadIdx.x; i < TOT;
         i += gridDim.x * blockDim.x) {
        int t  = i / (SQ * BH * (HD / 4));
        int r  = i - t * (SQ * BH * (HD / 4));
        int s  = r / (BH * (HD / 4));
        int r2 = r - s * (BH * (HD / 4));
        int bh = r2 >> 5;
        int c  = (r2 & 31) << 2;
        const float* src = (t == 0) ? Q : (t == 1) ? K : V;
        __half*      dst = (t == 0) ? g_qh : (t == 1) ? g_kh : g_vh;
        float4 v = *(const float4*)(src + (size_t)s * ROWSTRIDE + bh * HD + c);
        if (t == 0) { v.x *= SCL2; v.y *= SCL2; v.z *= SCL2; v.w *= SCL2; }
        __half2 h0 = __floats2half2_rn(v.x, v.y);
        __half2 h1 = __floats2half2_rn(v.z, v.w);
        uint2 u; u.x = *(uint32_t*)&h0; u.y = *(uint32_t*)&h1;
        *(uint2*)(dst + ((size_t)bh * SQ + s) * HD + c) = u;
    }
}

// ---------------- helpers ----------------
__device__ __forceinline__ uint32_t smem_u32(const void* p) {
    return (uint32_t)__cvta_generic_to_shared(p);
}
__device__ __forceinline__ void cp_async16(uint32_t dst, const void* src) {
    asm volatile("cp.async.cg.shared.global [%0], [%1], 16;" :: "r"(dst), "l"(src));
}
__device__ __forceinline__ void cp_commit() { asm volatile("cp.async.commit_group;"); }
template <int N> __device__ __forceinline__ void cp_wait() {
    asm volatile("cp.async.wait_group %0;" :: "n"(N));
}
__device__ __forceinline__ float ex2(float x) {
    float y; asm("ex2.approx.ftz.f32 %0, %1;" : "=f"(y) : "f"(x)); return y;
}
__device__ __forceinline__ void ldm_x4(uint32_t& r0, uint32_t& r1, uint32_t& r2, uint32_t& r3, uint32_t a) {
    asm volatile("ldmatrix.sync.aligned.m8n8.x4.shared.b16 {%0,%1,%2,%3}, [%4];"
                 : "=r"(r0), "=r"(r1), "=r"(r2), "=r"(r3) : "r"(a));
}
__device__ __forceinline__ void ldm_x4_t(uint32_t& r0, uint32_t& r1, uint32_t& r2, uint32_t& r3, uint32_t a) {
    asm volatile("ldmatrix.sync.aligned.m8n8.x4.trans.shared.b16 {%0,%1,%2,%3}, [%4];"
                 : "=r"(r0), "=r"(r1), "=r"(r2), "=r"(r3) : "r"(a));
}
__device__ __forceinline__ void mma16816(float* c, const uint32_t* a, uint32_t b0, uint32_t b1) {
    asm volatile("mma.sync.aligned.m16n8k16.row.col.f32.f16.f16.f32 "
                 "{%0,%1,%2,%3}, {%4,%5,%6,%7}, {%8,%9}, {%0,%1,%2,%3};"
                 : "+f"(c[0]), "+f"(c[1]), "+f"(c[2]), "+f"(c[3])
                 : "r"(a[0]), "r"(a[1]), "r"(a[2]), "r"(a[3]), "r"(b0), "r"(b1));
}
__device__ __forceinline__ uint32_t packh2(float x, float y) {
    __half2 h = __floats2half2_rn(x, y);
    return *(uint32_t*)&h;
}

// stage K,V tile (fp16) via cp.async
__device__ __forceinline__ void stage_tiles(int tid, int kb, const __half* Kh, const __half* Vh,
                                            char* sKs, char* sVs) {
    #pragma unroll
    for (int j = 0; j < 4; j++) {
        int i = tid + j * NTHREADS;          // 0..1023
        int r = i >> 4, ck = i & 15;
        size_t so = (size_t)(kb + r) * HD + ck * 8;
        cp_async16(smem_u32(sKs + r * PITCHB + ck * 16), Kh + so);
        cp_async16(smem_u32(sVs + r * PITCHB + ck * 16), Vh + so);
    }
}

__global__ void __launch_bounds__(NTHREADS, 1)
attn_fwd_kernel(float* __restrict__ Og) {
    extern __shared__ char smem[];
    __half* sQ = (__half*)(smem + OFF_Q);
    char* sK[3] = { smem + OFF_K0, smem + OFF_K1, smem + OFF_K2 };
    char* sV[3] = { smem + OFF_V0, smem + OFF_V1, smem + OFF_V2 };

    const int tid  = threadIdx.x;
    const int lane = tid & 31;
    const int warp = tid >> 5;

    const int q0 = blockIdx.x * BM;
    const int bh = blockIdx.y;
    const int bb = bh >> 4;
    const __half* Qh = g_qh + (size_t)bh * SQ * HD;
    const __half* Kh = g_kh + (size_t)bh * SQ * HD;
    const __half* Vh = g_vh + (size_t)bh * SQ * HD;

    // ---- prologue: async Q + tile0 (group 0), tile1 (group 1) ----
    #pragma unroll
    for (int j = 0; j < 8; j++) {
        int i = tid + j * NTHREADS;
        int r = i >> 4, ck = i & 15;
        cp_async16(smem_u32((char*)sQ + r * PITCHB + ck * 16),
                   Qh + (size_t)(q0 + r) * HD + ck * 8);
    }
    stage_tiles(tid, 0, Kh, Vh, sK[0], sV[0]);
    cp_commit();                          // group: Q + tile0
    stage_tiles(tid, BN, Kh, Vh, sK[1], sV[1]);
    cp_commit();                          // group: tile1

    const int g  = lane >> 2;
    const int tg = lane & 3;
    const int m0 = warp * 16;

    const int arow = m0 + (lane & 7) + ((lane >> 3) & 1) * 8;
    const int acol = (lane >> 4) * 8;
    const int krow = (lane & 7) + ((lane >> 4) & 1) * 8;
    const int kcol = ((lane >> 3) & 1) * 8;
    const int vrow = (lane & 7) + ((lane >> 3) & 1) * 8;
    const int vcol = (lane >> 4) * 8;

    const uint8_t* mrow0 = (const uint8_t*)g_mp
                         + ((size_t)bb * SQ + q0 + m0 + g) * MROWB;
    const uint8_t* mrow1 = mrow0 + (size_t)8 * MROWB;
    const int msh = 2 * tg;

    float o[16][4];
    #pragma unroll
    for (int t = 0; t < 16; t++) { o[t][0]=0.f; o[t][1]=0.f; o[t][2]=0.f; o[t][3]=0.f; }
    float l0a = 0.f, l0b = 0.f, l1a = 0.f, l1b = 0.f;

    cp_wait<1>();
    __syncthreads();
    uint32_t aq[8][4];
    #pragma unroll
    for (int kt = 0; kt < 8; kt++) {
        ldm_x4(aq[kt][0], aq[kt][1], aq[kt][2], aq[kt][3],
               smem_u32(sQ + arow * PITCH + kt * 16 + acol));
    }

    for (int it = 0; it < KVITERS; it++) {
        const int s = it % 3;
        __half* sKs = (__half*)sK[s];
        __half* sVs = (__half*)sV[s];

        // mask words for this tile (64 bits per row)
        uint2 w0 = *(const uint2*)(mrow0 + it * 8);
        uint2 w1 = *(const uint2*)(mrow1 + it * 8);
        const uint32_t wa0 = w0.x >> msh, wb0 = w0.y >> msh;
        const uint32_t wa1 = w1.x >> msh, wb1 = w1.y >> msh;

        cp_wait<1>();
        __syncthreads();   // tile it visible + WAR for staging below

        if (it + 2 < KVITERS) {
            stage_tiles(tid, (it + 2) * BN, Kh, Vh, sK[(it + 2) % 3], sV[(it + 2) % 3]);
        }
        cp_commit();

        // ---- S = Q @ K^T (log2 domain), kt-outer: 8 indep accumulators ----
        float c4[8][4];
        #pragma unroll
        for (int t = 0; t < 8; t++) { c4[t][0]=0.f; c4[t][1]=0.f; c4[t][2]=0.f; c4[t][3]=0.f; }
        #pragma unroll
        for (int kt = 0; kt < 8; kt++) {
            #pragma unroll
            for (int n16 = 0; n16 < 4; n16++) {
                uint32_t b0, b1, b2, b3;
                ldm_x4(b0, b1, b2, b3,
                       smem_u32(sKs + (n16 * 16 + krow) * PITCH + kt * 16 + kcol));
                mma16816(c4[2 * n16],     aq[kt], b0, b1);
                mma16816(c4[2 * n16 + 1], aq[kt], b2, b3);
            }
        }

        // softmax for n16-group j: writes 4 fragment words into pfp
        auto sm_group = [&](int j, uint32_t* pfp) {
            #pragma unroll
            for (int kk = 0; kk < 2; kk++) {
                int nt = 2 * j + kk;
                uint32_t ba  = (nt < 4) ? (wa0 >> (8 * nt)) : (wb0 >> (8 * (nt - 4)));
                uint32_t bb_ = (nt < 4) ? (wa1 >> (8 * nt)) : (wb1 >> (8 * (nt - 4)));
                float x0 = (ba  & 1u) ? -200.f : c4[nt][0];
                float x1 = (ba  & 2u) ? -200.f : c4[nt][1];
                float x2 = (bb_ & 1u) ? -200.f : c4[nt][2];
                float x3 = (bb_ & 2u) ? -200.f : c4[nt][3];
                float p0 = ex2(x0), p1 = ex2(x1), p2 = ex2(x2), p3 = ex2(x3);
                l0a += p0; l0b += p1;
                l1a += p2; l1b += p3;
                pfp[2 * kk]     = packh2(p0, p1);
                pfp[2 * kk + 1] = packh2(p2, p3);
            }
        };

        // ---- softmax pipelined into PV at n16-group granularity ----
        uint32_t pfA[4], pfB[4];
        sm_group(0, pfA);
        #pragma unroll
        for (int p = 0; p < 4; p++) {
            // compute next group's pf first: its MUFU/ALU ops overlap this group's PV MMAs
            if (p < 3) {
                if (p & 1) sm_group(p + 1, pfA);
                else       sm_group(p + 1, pfB);
            }
            const uint32_t* pfc = (p & 1) ? pfB : pfA;
            #pragma unroll
            for (int dn = 0; dn < 8; dn++) {
                uint32_t v0, v1, v2, v3;
                ldm_x4_t(v0, v1, v2, v3,
                         smem_u32(sVs + (p * 16 + vrow) * PITCH + dn * 16 + vcol));
                mma16816(o[2 * dn],     pfc, v0, v1);
                mma16816(o[2 * dn + 1], pfc, v2, v3);
            }
        }
    }

    // ---- epilogue: quad-reduce l, normalize, store ----
    float l0 = l0a + l0b;
    float l1 = l1a + l1b;
    l0 += __shfl_xor_sync(0xffffffffu, l0, 1);
    l0 += __shfl_xor_sync(0xffffffffu, l0, 2);
    l1 += __shfl_xor_sync(0xffffffffu, l1, 1);
    l1 += __shfl_xor_sync(0xffffffffu, l1, 2);
    float i0 = 1.f / l0;
    float i1 = 1.f / l1;

    float* orow0 = Og + (size_t)(q0 + m0 + g) * ROWSTRIDE + bh * HD;
    float* orow1 = orow0 + (size_t)8 * ROWSTRIDE;
    #pragma unroll
    for (int nt = 0; nt < 16; nt++) {
        float2 v0, v1;
        v0.x = o[nt][0] * i0; v0.y = o[nt][1] * i0;
        v1.x = o[nt][2] * i1; v1.y = o[nt][3] * i1;
        *(float2*)(orow0 + nt * 8 + 2 * tg) = v0;
        *(float2*)(orow1 + nt * 8 + 2 * tg) = v1;
    }
}

extern "C" void kernel_launch(void* const* d_in, const int* in_sizes, int n_in,
                              void* d_out, int out_size) {
    const float* Q = (const float*)d_in[0];
    const float* K = (const float*)d_in[1];
    const float* V = (const float*)d_in[2];
    const void*  M = d_in[3];
    float*       O = (float*)d_out;

    reset_flags_kernel<<<1, 1>>>();
    detect_kernel<<<512, 256>>>((const uint32_t*)M);
    pack_mask_kernel<<<1024, 256>>>(M);
    cvt_qkv_kernel<<<8192, 256>>>(Q, K, V);

    cudaFuncSetAttribute(attn_fwd_kernel, cudaFuncAttributeMaxDynamicSharedMemorySize, SMEM_BYTES);
    dim3 grid(SQ / BM, BH);
    attn_fwd_kernel<<<grid, NTHREADS, SMEM_BYTES>>>(O);
}

// round 12
// speedup vs baseline: 1.5028x; 1.0487x over previous
#include <cuda_runtime.h>
#include <cuda_fp16.h>
#include <cstdint>

// ---------------- problem constants ----------------
#define SQ   2048
#define NB   2
#define NH   16
#define BH   (NB * NH)             // 32
#define HD   128
#define ROWSTRIDE (BH * HD)        // 4096 floats
#define MASK_ELEMS (NB * SQ * SQ)  // 8388608
#define MROWB (SQ / 8)             // 256 bytes per packed mask row

// ---------------- tiling ----------------
#define BM        64               // q rows per CTA (4 warps x 16)
#define BN        64
#define NTHREADS  128
#define PITCH     136              // half elems per smem row (272B), conflict-free ldmatrix
#define PITCHB    272
#define KVITERS   (SQ / BN)        // 32

#define SCALE  0.08838834764831845f       // 1/sqrt(128)
#define LOG2E  1.4426950408889634f
#define SCL2   (SCALE * LOG2E)            // folded into Q in prepass

// smem per CTA: Q | K0 V0 | K1 V1   (double-buffered KV) = 87040 B -> 2 CTAs/SM
#define TILE    17408              // 64 * 272
#define OFF_Q   0
#define OFF_K0  17408
#define OFF_V0  (OFF_K0 + TILE)
#define OFF_K1  (OFF_V0 + TILE)
#define OFF_V1  (OFF_K1 + TILE)
#define SMEM_BYTES (OFF_V1 + TILE)   // 87040

// ---------------- global scratch ----------------
__device__ __half   g_qh[(size_t)BH * SQ * HD];   // Q prescaled by SCL2
__device__ __half   g_kh[(size_t)BH * SQ * HD];
__device__ __half   g_vh[(size_t)BH * SQ * HD];
__device__ uint32_t g_mp[MASK_ELEMS / 32];        // packed mask bits
__device__ int      g_flags[2];

__global__ void reset_flags_kernel() { g_flags[0] = 0; g_flags[1] = 0; }

#define DETECT_WORDS (MASK_ELEMS / 4)
__global__ void detect_kernel(const uint32_t* __restrict__ m) {
    int f_f32 = 0, f_u8 = 0;
    for (int i = blockIdx.x * blockDim.x + threadIdx.x; i < DETECT_WORDS;
         i += gridDim.x * blockDim.x) {
        uint32_t w = m[i];
        if (w == 0x3F800000u) f_f32 = 1;
        else if (w > 1u)      f_u8  = 1;
    }
    if (f_f32) atomicOr(&g_flags[0], 1);
    if (f_u8)  atomicOr(&g_flags[1], 1);
}

__global__ void pack_mask_kernel(const void* __restrict__ m) {
    const int u8mode = (!g_flags[0] && g_flags[1]);
    const int NW = MASK_ELEMS / 32;
    for (int w = blockIdx.x * blockDim.x + threadIdx.x; w < NW;
         w += gridDim.x * blockDim.x) {
        uint32_t bits = 0;
        if (u8mode) {
            const uint8_t* p = (const uint8_t*)m + (size_t)w * 32;
            #pragma unroll
            for (int j = 0; j < 32; j++) bits |= (uint32_t)(p[j] != 0) << j;
        } else {
            const uint32_t* p = (const uint32_t*)m + (size_t)w * 32;
            #pragma unroll
            for (int j = 0; j < 32; j++) bits |= (uint32_t)(p[j] != 0u) << j;
        }
        g_mp[w] = bits;
    }
}

// fp32 [s][b][h][d] -> fp16 [bh][s][d]; Q additionally scaled by SCL2
__global__ void cvt_qkv_kernel(const float* __restrict__ Q, const float* __restrict__ K,
                               const float* __restrict__ V) {
    const int TOT = 3 * SQ * BH * (HD / 4);
    for (int i = blockIdx.x * blockDim.x + threadIdx.x; i < TOT;
         i += gridDim.x * blockDim.x) {
        int t  = i / (SQ * BH * (HD / 4));
        int r  = i - t * (SQ * BH * (HD / 4));
        int s  = r / (BH * (HD / 4));
        int r2 = r - s * (BH * (HD / 4));
        int bh = r2 >> 5;
        int c  = (r2 & 31) << 2;
        const float* src = (t == 0) ? Q : (t == 1) ? K : V;
        __half*      dst = (t == 0) ? g_qh : (t == 1) ? g_kh : g_vh;
        float4 v = *(const float4*)(src + (size_t)s * ROWSTRIDE + bh * HD + c);
        if (t == 0) { v.x *= SCL2; v.y *= SCL2; v.z *= SCL2; v.w *= SCL2; }
        __half2 h0 = __floats2half2_rn(v.x, v.y);
        __half2 h1 = __floats2half2_rn(v.z, v.w);
        uint2 u; u.x = *(uint32_t*)&h0; u.y = *(uint32_t*)&h1;
        *(uint2*)(dst + ((size_t)bh * SQ + s) * HD + c) = u;
    }
}

// ---------------- helpers ----------------
__device__ __forceinline__ uint32_t smem_u32(const void* p) {
    return (uint32_t)__cvta_generic_to_shared(p);
}
__device__ __forceinline__ void cp_async16(uint32_t dst, const void* src) {
    asm volatile("cp.async.cg.shared.global [%0], [%1], 16;" :: "r"(dst), "l"(src));
}
__device__ __forceinline__ void cp_commit() { asm volatile("cp.async.commit_group;"); }
template <int N> __device__ __forceinline__ void cp_wait() {
    asm volatile("cp.async.wait_group %0;" :: "n"(N));
}
__device__ __forceinline__ float ex2(float x) {
    float y; asm("ex2.approx.ftz.f32 %0, %1;" : "=f"(y) : "f"(x)); return y;
}
__device__ __forceinline__ void ldm_x4(uint32_t& r0, uint32_t& r1, uint32_t& r2, uint32_t& r3, uint32_t a) {
    asm volatile("ldmatrix.sync.aligned.m8n8.x4.shared.b16 {%0,%1,%2,%3}, [%4];"
                 : "=r"(r0), "=r"(r1), "=r"(r2), "=r"(r3) : "r"(a));
}
__device__ __forceinline__ void ldm_x4_t(uint32_t& r0, uint32_t& r1, uint32_t& r2, uint32_t& r3, uint32_t a) {
    asm volatile("ldmatrix.sync.aligned.m8n8.x4.trans.shared.b16 {%0,%1,%2,%3}, [%4];"
                 : "=r"(r0), "=r"(r1), "=r"(r2), "=r"(r3) : "r"(a));
}
__device__ __forceinline__ void mma16816(float* c, const uint32_t* a, uint32_t b0, uint32_t b1) {
    asm volatile("mma.sync.aligned.m16n8k16.row.col.f32.f16.f16.f32 "
                 "{%0,%1,%2,%3}, {%4,%5,%6,%7}, {%8,%9}, {%0,%1,%2,%3};"
                 : "+f"(c[0]), "+f"(c[1]), "+f"(c[2]), "+f"(c[3])
                 : "r"(a[0]), "r"(a[1]), "r"(a[2]), "r"(a[3]), "r"(b0), "r"(b1));
}
__device__ __forceinline__ uint32_t packh2(float x, float y) {
    __half2 h = __floats2half2_rn(x, y);
    return *(uint32_t*)&h;
}

// stage K,V tile (fp16) via cp.async (128 threads)
__device__ __forceinline__ void stage_tiles(int tid, int kb, const __half* Kh, const __half* Vh,
                                            char* sKs, char* sVs) {
    #pragma unroll
    for (int j = 0; j < 8; j++) {
        int i = tid + j * NTHREADS;          // 0..1023
        int r = i >> 4, ck = i & 15;
        size_t so = (size_t)(kb + r) * HD + ck * 8;
        cp_async16(smem_u32(sKs + r * PITCHB + ck * 16), Kh + so);
        cp_async16(smem_u32(sVs + r * PITCHB + ck * 16), Vh + so);
    }
}

__global__ void __launch_bounds__(NTHREADS, 2)
attn_fwd_kernel(float* __restrict__ Og) {
    extern __shared__ char smem[];
    __half* sQ = (__half*)(smem + OFF_Q);
    char* sK[2] = { smem + OFF_K0, smem + OFF_K1 };
    char* sV[2] = { smem + OFF_V0, smem + OFF_V1 };

    const int tid  = threadIdx.x;
    const int lane = tid & 31;
    const int warp = tid >> 5;

    const int q0 = blockIdx.x * BM;
    const int bh = blockIdx.y;
    const int bb = bh >> 4;
    const __half* Qh = g_qh + (size_t)bh * SQ * HD;
    const __half* Kh = g_kh + (size_t)bh * SQ * HD;
    const __half* Vh = g_vh + (size_t)bh * SQ * HD;

    // ---- prologue: async Q (64 rows) + tile0 (group 0), tile1 (group 1) ----
    #pragma unroll
    for (int j = 0; j < 8; j++) {
        int i = tid + j * NTHREADS;          // 0..1023
        int r = i >> 4, ck = i & 15;
        cp_async16(smem_u32((char*)sQ + r * PITCHB + ck * 16),
                   Qh + (size_t)(q0 + r) * HD + ck * 8);
    }
    stage_tiles(tid, 0, Kh, Vh, sK[0], sV[0]);
    cp_commit();                          // group: Q + tile0
    stage_tiles(tid, BN, Kh, Vh, sK[1], sV[1]);
    cp_commit();                          // group: tile1

    const int g  = lane >> 2;
    const int tg = lane & 3;
    const int m0 = warp * 16;             // warps 0..3 -> rows 0..63

    const int arow = m0 + (lane & 7) + ((lane >> 3) & 1) * 8;
    const int acol = (lane >> 4) * 8;
    const int krow = (lane & 7) + ((lane >> 4) & 1) * 8;
    const int kcol = ((lane >> 3) & 1) * 8;
    const int vrow = (lane & 7) + ((lane >> 3) & 1) * 8;
    const int vcol = (lane >> 4) * 8;

    const uint8_t* mrow0 = (const uint8_t*)g_mp
                         + ((size_t)bb * SQ + q0 + m0 + g) * MROWB;
    const uint8_t* mrow1 = mrow0 + (size_t)8 * MROWB;
    const int msh = 2 * tg;

    float o[16][4];
    #pragma unroll
    for (int t = 0; t < 16; t++) { o[t][0]=0.f; o[t][1]=0.f; o[t][2]=0.f; o[t][3]=0.f; }
    float l0a = 0.f, l0b = 0.f, l1a = 0.f, l1b = 0.f;

    cp_wait<1>();          // Q + tile0 ready
    __syncthreads();
    uint32_t aq[8][4];
    #pragma unroll
    for (int kt = 0; kt < 8; kt++) {
        ldm_x4(aq[kt][0], aq[kt][1], aq[kt][2], aq[kt][3],
               smem_u32(sQ + arow * PITCH + kt * 16 + acol));
    }

    for (int it = 0; it < KVITERS; it++) {
        const int s = it & 1;
        __half* sKs = (__half*)sK[s];
        __half* sVs = (__half*)sV[s];

        // mask words for this tile (64 bits per row)
        uint2 w0 = *(const uint2*)(mrow0 + it * 8);
        uint2 w1 = *(const uint2*)(mrow1 + it * 8);
        const uint32_t wa0 = w0.x >> msh, wb0 = w0.y >> msh;
        const uint32_t wa1 = w1.x >> msh, wb1 = w1.y >> msh;

        cp_wait<1>();          // tile it arrived (committed 2 groups back)
        __syncthreads();       // visibility across warps

        // ---- S = Q @ K^T (log2 domain), kt-outer: 8 indep accumulators ----
        float c4[8][4];
        #pragma unroll
        for (int t = 0; t < 8; t++) { c4[t][0]=0.f; c4[t][1]=0.f; c4[t][2]=0.f; c4[t][3]=0.f; }
        #pragma unroll
        for (int kt = 0; kt < 8; kt++) {
            #pragma unroll
            for (int n16 = 0; n16 < 4; n16++) {
                uint32_t b0, b1, b2, b3;
                ldm_x4(b0, b1, b2, b3,
                       smem_u32(sKs + (n16 * 16 + krow) * PITCH + kt * 16 + kcol));
                mma16816(c4[2 * n16],     aq[kt], b0, b1);
                mma16816(c4[2 * n16 + 1], aq[kt], b2, b3);
            }
        }

        // ---- mask + exp2 + pack ----
        uint32_t pf[4][4];
        #pragma unroll
        for (int nt = 0; nt < 8; nt++) {
            uint32_t ba  = (nt < 4) ? (wa0 >> (8 * nt)) : (wb0 >> (8 * (nt - 4)));
            uint32_t bb_ = (nt < 4) ? (wa1 >> (8 * nt)) : (wb1 >> (8 * (nt - 4)));
            float x0 = (ba  & 1u) ? -200.f : c4[nt][0];
            float x1 = (ba  & 2u) ? -200.f : c4[nt][1];
            float x2 = (bb_ & 1u) ? -200.f : c4[nt][2];
            float x3 = (bb_ & 2u) ? -200.f : c4[nt][3];
            float p0 = ex2(x0), p1 = ex2(x1), p2 = ex2(x2), p3 = ex2(x3);
            l0a += p0; l0b += p1;
            l1a += p2; l1b += p3;
            pf[nt >> 1][(nt & 1) * 2]     = packh2(p0, p1);
            pf[nt >> 1][(nt & 1) * 2 + 1] = packh2(p2, p3);
        }

        // ---- O += P @ V, j-outer: 16 indep accumulators between reuses ----
        #pragma unroll
        for (int j = 0; j < 4; j++) {
            #pragma unroll
            for (int dn = 0; dn < 8; dn++) {
                uint32_t v0, v1, v2, v3;
                ldm_x4_t(v0, v1, v2, v3,
                         smem_u32(sVs + (j * 16 + vrow) * PITCH + dn * 16 + vcol));
                mma16816(o[2 * dn],     pf[j], v0, v1);
                mma16816(o[2 * dn + 1], pf[j], v2, v3);
            }
        }

        // ---- buffer s is free now: stage tile it+2 into it ----
        __syncthreads();       // all warps done reading buffer s
        if (it + 2 < KVITERS) {
            stage_tiles(tid, (it + 2) * BN, Kh, Vh, sK[s], sV[s]);
        }
        cp_commit();           // keep group count in lockstep
    }

    // ---- epilogue: quad-reduce l, normalize, store ----
    float l0 = l0a + l0b;
    float l1 = l1a + l1b;
    l0 += __shfl_xor_sync(0xffffffffu, l0, 1);
    l0 += __shfl_xor_sync(0xffffffffu, l0, 2);
    l1 += __shfl_xor_sync(0xffffffffu, l1, 1);
    l1 += __shfl_xor_sync(0xffffffffu, l1, 2);
    float i0 = 1.f / l0;
    float i1 = 1.f / l1;

    float* orow0 = Og + (size_t)(q0 + m0 + g) * ROWSTRIDE + bh * HD;
    float* orow1 = orow0 + (size_t)8 * ROWSTRIDE;
    #pragma unroll
    for (int nt = 0; nt < 16; nt++) {
        float2 v0, v1;
        v0.x = o[nt][0] * i0; v0.y = o[nt][1] * i0;
        v1.x = o[nt][2] * i1; v1.y = o[nt][3] * i1;
        *(float2*)(orow0 + nt * 8 + 2 * tg) = v0;
        *(float2*)(orow1 + nt * 8 + 2 * tg) = v1;
    }
}

extern "C" void kernel_launch(void* const* d_in, const int* in_sizes, int n_in,
                              void* d_out, int out_size) {
    const float* Q = (const float*)d_in[0];
    const float* K = (const float*)d_in[1];
    const float* V = (const float*)d_in[2];
    const void*  M = d_in[3];
    float*       O = (float*)d_out;

    reset_flags_kernel<<<1, 1>>>();
    detect_kernel<<<512, 256>>>((const uint32_t*)M);
    pack_mask_kernel<<<1024, 256>>>(M);
    cvt_qkv_kernel<<<8192, 256>>>(Q, K, V);

    cudaFuncSetAttribute(attn_fwd_kernel, cudaFuncAttributeMaxDynamicSharedMemorySize, SMEM_BYTES);
    dim3 grid(SQ / BM, BH);
    attn_fwd_kernel<<<grid, NTHREADS, SMEM_BYTES>>>(O);
}

// round 13
// speedup vs baseline: 1.5967x; 1.0625x over previous
#include <cuda_runtime.h>
#include <cuda_fp16.h>
#include <cstdint>

// ---------------- problem constants ----------------
#define SQ   2048
#define NB   2
#define NH   16
#define BH   (NB * NH)             // 32
#define HD   128
#define ROWSTRIDE (BH * HD)        // 4096 floats
#define MASK_ELEMS (NB * SQ * SQ)  // 8388608
#define MROWB (SQ / 8)             // 256 bytes per packed mask row

// ---------------- tiling ----------------
#define BM        64               // q rows per CTA (4 warps x 16)
#define BN        64
#define NTHREADS  128
#define KVITERS   (SQ / BN)        // 32

#define SCALE  0.08838834764831845f       // 1/sqrt(128)
#define LOG2E  1.4426950408889634f
#define SCL2   (SCALE * LOG2E)            // folded into Q in prepass

// smem per CTA (swizzled, 256B rows, no padding):
//   Q (16K) | K0 V0 K1 V1 K2 V2 (6 x 16K)  = 114688 B -> 2 CTAs/SM
#define TILE    16384
#define OFF_Q   0
#define OFF_KV  16384
#define SMEM_BYTES (OFF_Q + 7 * TILE)   // 114688

// swizzled byte offset of 16B chunk ck (0..15) in row r (256B rows)
#define SWOFF(r, ck) (((r) << 8) + ((((ck) ^ ((r) & 7))) << 4))

// ---------------- global scratch ----------------
__device__ __half   g_qh[(size_t)BH * SQ * HD];   // Q prescaled by SCL2
__device__ __half   g_kh[(size_t)BH * SQ * HD];
__device__ __half   g_vh[(size_t)BH * SQ * HD];
__device__ uint32_t g_mp[MASK_ELEMS / 32];        // packed mask bits
__device__ int      g_flags[2] = {0, 0};          // static init; detect only ORs (idempotent)

#define DETECT_WORDS (MASK_ELEMS / 4)
__global__ void detect_kernel(const uint32_t* __restrict__ m) {
    int f_f32 = 0, f_u8 = 0;
    for (int i = blockIdx.x * blockDim.x + threadIdx.x; i < DETECT_WORDS;
         i += gridDim.x * blockDim.x) {
        uint32_t w = m[i];
        if (w == 0x3F800000u) f_f32 = 1;
        else if (w > 1u)      f_u8  = 1;
    }
    if (f_f32) atomicOr(&g_flags[0], 1);
    if (f_u8)  atomicOr(&g_flags[1], 1);
}

// fused prep: blocks [0,1024) pack mask bits; blocks [1024,9216) convert QKV
#define PACK_BLOCKS 1024
__global__ void prep_kernel(const void* __restrict__ m,
                            const float* __restrict__ Q, const float* __restrict__ K,
                            const float* __restrict__ V) {
    if (blockIdx.x < PACK_BLOCKS) {
        const int u8mode = (!g_flags[0] && g_flags[1]);
        const int w = blockIdx.x * blockDim.x + threadIdx.x;   // exactly MASK_ELEMS/32 threads
        uint32_t bits = 0;
        if (u8mode) {
            const uint8_t* p = (const uint8_t*)m + (size_t)w * 32;
            #pragma unroll
            for (int j = 0; j < 32; j++) bits |= (uint32_t)(p[j] != 0) << j;
        } else {
            const uint32_t* p = (const uint32_t*)m + (size_t)w * 32;
            #pragma unroll
            for (int j = 0; j < 32; j++) bits |= (uint32_t)(p[j] != 0u) << j;
        }
        g_mp[w] = bits;
    } else {
        const int TOT = 3 * SQ * BH * (HD / 4);
        const int base = (blockIdx.x - PACK_BLOCKS) * blockDim.x + threadIdx.x;
        const int stride = (gridDim.x - PACK_BLOCKS) * blockDim.x;
        for (int i = base; i < TOT; i += stride) {
            int t  = i / (SQ * BH * (HD / 4));
            int r  = i - t * (SQ * BH * (HD / 4));
            int s  = r / (BH * (HD / 4));
            int r2 = r - s * (BH * (HD / 4));
            int bh = r2 >> 5;
            int c  = (r2 & 31) << 2;
            const float* src = (t == 0) ? Q : (t == 1) ? K : V;
            __half*      dst = (t == 0) ? g_qh : (t == 1) ? g_kh : g_vh;
            float4 v = *(const float4*)(src + (size_t)s * ROWSTRIDE + bh * HD + c);
            if (t == 0) { v.x *= SCL2; v.y *= SCL2; v.z *= SCL2; v.w *= SCL2; }
            __half2 h0 = __floats2half2_rn(v.x, v.y);
            __half2 h1 = __floats2half2_rn(v.z, v.w);
            uint2 u; u.x = *(uint32_t*)&h0; u.y = *(uint32_t*)&h1;
            *(uint2*)(dst + ((size_t)bh * SQ + s) * HD + c) = u;
        }
    }
}

// ---------------- helpers ----------------
__device__ __forceinline__ uint32_t smem_u32(const void* p) {
    return (uint32_t)__cvta_generic_to_shared(p);
}
__device__ __forceinline__ void cp_async16(uint32_t dst, const void* src) {
    asm volatile("cp.async.cg.shared.global [%0], [%1], 16;" :: "r"(dst), "l"(src));
}
__device__ __forceinline__ void cp_commit() { asm volatile("cp.async.commit_group;"); }
template <int N> __device__ __forceinline__ void cp_wait() {
    asm volatile("cp.async.wait_group %0;" :: "n"(N));
}
__device__ __forceinline__ float ex2(float x) {
    float y; asm("ex2.approx.ftz.f32 %0, %1;" : "=f"(y) : "f"(x)); return y;
}
__device__ __forceinline__ void ldm_x4(uint32_t& r0, uint32_t& r1, uint32_t& r2, uint32_t& r3, uint32_t a) {
    asm volatile("ldmatrix.sync.aligned.m8n8.x4.shared.b16 {%0,%1,%2,%3}, [%4];"
                 : "=r"(r0), "=r"(r1), "=r"(r2), "=r"(r3) : "r"(a));
}
__device__ __forceinline__ void ldm_x4_t(uint32_t& r0, uint32_t& r1, uint32_t& r2, uint32_t& r3, uint32_t a) {
    asm volatile("ldmatrix.sync.aligned.m8n8.x4.trans.shared.b16 {%0,%1,%2,%3}, [%4];"
                 : "=r"(r0), "=r"(r1), "=r"(r2), "=r"(r3) : "r"(a));
}
__device__ __forceinline__ void mma16816(float* c, const uint32_t* a, uint32_t b0, uint32_t b1) {
    asm volatile("mma.sync.aligned.m16n8k16.row.col.f32.f16.f16.f32 "
                 "{%0,%1,%2,%3}, {%4,%5,%6,%7}, {%8,%9}, {%0,%1,%2,%3};"
                 : "+f"(c[0]), "+f"(c[1]), "+f"(c[2]), "+f"(c[3])
                 : "r"(a[0]), "r"(a[1]), "r"(a[2]), "r"(a[3]), "r"(b0), "r"(b1));
}
__device__ __forceinline__ uint32_t packh2(float x, float y) {
    __half2 h = __floats2half2_rn(x, y);
    return *(uint32_t*)&h;
}

// stage K,V tile (fp16, swizzled) via cp.async (128 threads)
__device__ __forceinline__ void stage_tiles(int tid, int kb, const __half* Kh, const __half* Vh,
                                            char* sKs, char* sVs) {
    #pragma unroll
    for (int j = 0; j < 8; j++) {
        int i = tid + j * NTHREADS;          // 0..1023
        int r = i >> 4, ck = i & 15;
        size_t so = (size_t)(kb + r) * HD + ck * 8;
        uint32_t off = SWOFF(r, ck);
        cp_async16(smem_u32(sKs + off), Kh + so);
        cp_async16(smem_u32(sVs + off), Vh + so);
    }
}

__global__ void __launch_bounds__(NTHREADS, 2)
attn_fwd_kernel(float* __restrict__ Og) {
    extern __shared__ char smem[];
    char* sQ = smem + OFF_Q;
    char* sK[3] = { smem + OFF_KV,            smem + OFF_KV + 2 * TILE, smem + OFF_KV + 4 * TILE };
    char* sV[3] = { smem + OFF_KV + TILE,     smem + OFF_KV + 3 * TILE, smem + OFF_KV + 5 * TILE };

    const int tid  = threadIdx.x;
    const int lane = tid & 31;
    const int warp = tid >> 5;

    const int q0 = blockIdx.x * BM;
    const int bh = blockIdx.y;
    const int bb = bh >> 4;
    const __half* Qh = g_qh + (size_t)bh * SQ * HD;
    const __half* Kh = g_kh + (size_t)bh * SQ * HD;
    const __half* Vh = g_vh + (size_t)bh * SQ * HD;

    // ---- prologue: async Q (64 rows) + tile0 (group 0), tile1 (group 1) ----
    #pragma unroll
    for (int j = 0; j < 8; j++) {
        int i = tid + j * NTHREADS;          // 0..1023
        int r = i >> 4, ck = i & 15;
        cp_async16(smem_u32(sQ + SWOFF(r, ck)), Qh + (size_t)(q0 + r) * HD + ck * 8);
    }
    stage_tiles(tid, 0, Kh, Vh, sK[0], sV[0]);
    cp_commit();                          // group: Q + tile0
    stage_tiles(tid, BN, Kh, Vh, sK[1], sV[1]);
    cp_commit();                          // group: tile1

    const int g  = lane >> 2;
    const int tg = lane & 3;
    const int m0 = warp * 16;             // warps 0..3 -> rows 0..63

    // lane row indices for fragment loads
    const int arow = m0 + (lane & 7) + ((lane >> 3) & 1) * 8;
    const int ach  = (lane >> 4);         // acol/8: 0 or 1
    const int krow = (lane & 7) + ((lane >> 4) & 1) * 8;
    const int kch  = (lane >> 3) & 1;     // kcol/8
    const int vrow = (lane & 7) + ((lane >> 3) & 1) * 8;
    const int vch  = (lane >> 4);         // vcol/8

    const uint8_t* mrow0 = (const uint8_t*)g_mp
                         + ((size_t)bb * SQ + q0 + m0 + g) * MROWB;
    const uint8_t* mrow1 = mrow0 + (size_t)8 * MROWB;
    const int msh = 2 * tg;

    float o[16][4];
    #pragma unroll
    for (int t = 0; t < 16; t++) { o[t][0]=0.f; o[t][1]=0.f; o[t][2]=0.f; o[t][3]=0.f; }
    float l0a = 0.f, l0b = 0.f, l1a = 0.f, l1b = 0.f;

    cp_wait<1>();          // Q + tile0 ready
    __syncthreads();
    uint32_t aq[8][4];
    #pragma unroll
    for (int kt = 0; kt < 8; kt++) {
        ldm_x4(aq[kt][0], aq[kt][1], aq[kt][2], aq[kt][3],
               smem_u32(sQ + SWOFF(arow, kt * 2 + ach)));
    }

    for (int it = 0; it < KVITERS; it++) {
        const int s = it % 3;
        char* sKs = sK[s];
        char* sVs = sV[s];

        // mask words for this tile (64 bits per row)
        uint2 w0 = *(const uint2*)(mrow0 + it * 8);
        uint2 w1 = *(const uint2*)(mrow1 + it * 8);
        const uint32_t wa0 = w0.x >> msh, wb0 = w0.y >> msh;
        const uint32_t wa1 = w1.x >> msh, wb1 = w1.y >> msh;

        cp_wait<1>();          // tile it arrived (committed 2 groups back)
        __syncthreads();       // visibility + WAR separation (single barrier per iter)

        // stage tile it+2 into buffer (it+2)%3 (last read in iter it-1; safe after sync)
        if (it + 2 < KVITERS) {
            stage_tiles(tid, (it + 2) * BN, Kh, Vh, sK[(it + 2) % 3], sV[(it + 2) % 3]);
        }
        cp_commit();

        // ---- S = Q @ K^T (log2 domain), kt-outer: 8 indep accumulators ----
        float c4[8][4];
        #pragma unroll
        for (int t = 0; t < 8; t++) { c4[t][0]=0.f; c4[t][1]=0.f; c4[t][2]=0.f; c4[t][3]=0.f; }
        #pragma unroll
        for (int kt = 0; kt < 8; kt++) {
            #pragma unroll
            for (int n16 = 0; n16 < 4; n16++) {
                uint32_t b0, b1, b2, b3;
                ldm_x4(b0, b1, b2, b3,
                       smem_u32(sKs + SWOFF(n16 * 16 + krow, kt * 2 + kch)));
                mma16816(c4[2 * n16],     aq[kt], b0, b1);
                mma16816(c4[2 * n16 + 1], aq[kt], b2, b3);
            }
        }

        // ---- mask + exp2 + pack ----
        uint32_t pf[4][4];
        #pragma unroll
        for (int nt = 0; nt < 8; nt++) {
            uint32_t ba  = (nt < 4) ? (wa0 >> (8 * nt)) : (wb0 >> (8 * (nt - 4)));
            uint32_t bb_ = (nt < 4) ? (wa1 >> (8 * nt)) : (wb1 >> (8 * (nt - 4)));
            float x0 = (ba  & 1u) ? -200.f : c4[nt][0];
            float x1 = (ba  & 2u) ? -200.f : c4[nt][1];
            float x2 = (bb_ & 1u) ? -200.f : c4[nt][2];
            float x3 = (bb_ & 2u) ? -200.f : c4[nt][3];
            float p0 = ex2(x0), p1 = ex2(x1), p2 = ex2(x2), p3 = ex2(x3);
            l0a += p0; l0b += p1;
            l1a += p2; l1b += p3;
            pf[nt >> 1][(nt & 1) * 2]     = packh2(p0, p1);
            pf[nt >> 1][(nt & 1) * 2 + 1] = packh2(p2, p3);
        }

        // ---- O += P @ V, j-outer: 16 indep accumulators between reuses ----
        #pragma unroll
        for (int j = 0; j < 4; j++) {
            #pragma unroll
            for (int dn = 0; dn < 8; dn++) {
                uint32_t v0, v1, v2, v3;
                ldm_x4_t(v0, v1, v2, v3,
                         smem_u32(sVs + SWOFF(j * 16 + vrow, dn * 2 + vch)));
                mma16816(o[2 * dn],     pf[j], v0, v1);
                mma16816(o[2 * dn + 1], pf[j], v2, v3);
            }
        }
    }

    // ---- epilogue: quad-reduce l, normalize, store ----
    float l0 = l0a + l0b;
    float l1 = l1a + l1b;
    l0 += __shfl_xor_sync(0xffffffffu, l0, 1);
    l0 += __shfl_xor_sync(0xffffffffu, l0, 2);
    l1 += __shfl_xor_sync(0xffffffffu, l1, 1);
    l1 += __shfl_xor_sync(0xffffffffu, l1, 2);
    float i0 = 1.f / l0;
    float i1 = 1.f / l1;

    float* orow0 = Og + (size_t)(q0 + m0 + g) * ROWSTRIDE + bh * HD;
    float* orow1 = orow0 + (size_t)8 * ROWSTRIDE;
    #pragma unroll
    for (int nt = 0; nt < 16; nt++) {
        float2 v0, v1;
        v0.x = o[nt][0] * i0; v0.y = o[nt][1] * i0;
        v1.x = o[nt][2] * i1; v1.y = o[nt][3] * i1;
        *(float2*)(orow0 + nt * 8 + 2 * tg) = v0;
        *(float2*)(orow1 + nt * 8 + 2 * tg) = v1;
    }
}

extern "C" void kernel_launch(void* const* d_in, const int* in_sizes, int n_in,
                              void* d_out, int out_size) {
    const float* Q = (const float*)d_in[0];
    const float* K = (const float*)d_in[1];
    const float* V = (const float*)d_in[2];
    const void*  M = d_in[3];
    float*       O = (float*)d_out;

    detect_kernel<<<512, 256>>>((const uint32_t*)M);
    prep_kernel<<<PACK_BLOCKS + 8192, 256>>>(M, Q, K, V);

    cudaFuncSetAttribute(attn_fwd_kernel, cudaFuncAttributeMaxDynamicSharedMemorySize, SMEM_BYTES);
    dim3 grid(SQ / BM, BH);
    attn_fwd_kernel<<<grid, NTHREADS, SMEM_BYTES>>>(O);
}

// round 14
// speedup vs baseline: 1.6253x; 1.0180x over previous
#include <cuda_runtime.h>
#include <cuda_fp16.h>
#include <cstdint>

// ---------------- problem constants ----------------
#define SQ   2048
#define NB   2
#define NH   16
#define BH   (NB * NH)             // 32
#define HD   128
#define ROWSTRIDE (BH * HD)        // 4096 floats
#define MASK_ELEMS (NB * SQ * SQ)  // 8388608
#define MROWB (SQ / 8)             // 256 bytes per packed mask row

// ---------------- tiling ----------------
#define BM        64               // q rows per CTA (4 warps x 16)
#define BN        64
#define NTHREADS  128
#define KVITERS   (SQ / BN)        // 32

#define SCALE  0.08838834764831845f       // 1/sqrt(128)
#define LOG2E  1.4426950408889634f
#define SCL2   (SCALE * LOG2E)            // folded into Q in prepass

// smem per CTA (swizzled, 256B rows, no padding):
//   Q (16K) | K0 V0 K1 V1 K2 V2 (6 x 16K)  = 114688 B -> 2 CTAs/SM
#define TILE    16384
#define OFF_Q   0
#define OFF_KV  16384
#define SMEM_BYTES (OFF_Q + 7 * TILE)   // 114688

// swizzled byte offset of 16B chunk ck (0..15) in row r (256B rows)
#define SWOFF(r, ck) (((r) << 8) + ((((ck) ^ ((r) & 7))) << 4))

// ---------------- global scratch ----------------
__device__ __half   g_qh[(size_t)BH * SQ * HD];   // Q prescaled by SCL2
__device__ __half   g_kh[(size_t)BH * SQ * HD];
__device__ __half   g_vh[(size_t)BH * SQ * HD];
__device__ uint32_t g_mp[MASK_ELEMS / 32];        // packed mask bits
__device__ int      g_flags[2] = {0, 0};          // static init; detect only ORs (idempotent)

// sample-based dtype detect: scan first 1MB (262144 words). For u8-packed masks
// P(no word>1 in 262144 words) ~ 0.73^262144 ~ 0; for fp32, P(no 1.0f) ~ 0.
#define DETECT_WORDS 262144
__global__ void detect_kernel(const uint32_t* __restrict__ m) {
    int f_f32 = 0, f_u8 = 0;
    int i = blockIdx.x * blockDim.x + threadIdx.x;    // 65536 threads x 4 words
    #pragma unroll
    for (int j = 0; j < 4; j++) {
        uint32_t w = m[i + j * 65536];
        if (w == 0x3F800000u) f_f32 = 1;
        else if (w > 1u)      f_u8  = 1;
    }
    if (f_f32) atomicOr(&g_flags[0], 1);
    if (f_u8)  atomicOr(&g_flags[1], 1);
}

// fused prep: blocks [0,1024) pack mask bits; blocks [1024,9216) convert QKV
#define PACK_BLOCKS 1024
__global__ void prep_kernel(const void* __restrict__ m,
                            const float* __restrict__ Q, const float* __restrict__ K,
                            const float* __restrict__ V) {
    if (blockIdx.x < PACK_BLOCKS) {
        const int u8mode = (!g_flags[0] && g_flags[1]);
        const int w = blockIdx.x * blockDim.x + threadIdx.x;   // exactly MASK_ELEMS/32 threads
        uint32_t bits = 0;
        if (u8mode) {
            const uint8_t* p = (const uint8_t*)m + (size_t)w * 32;
            #pragma unroll
            for (int j = 0; j < 32; j++) bits |= (uint32_t)(p[j] != 0) << j;
        } else {
            const uint32_t* p = (const uint32_t*)m + (size_t)w * 32;
            #pragma unroll
            for (int j = 0; j < 32; j++) bits |= (uint32_t)(p[j] != 0u) << j;
        }
        g_mp[w] = bits;
    } else {
        const int TOT = 3 * SQ * BH * (HD / 4);
        const int base = (blockIdx.x - PACK_BLOCKS) * blockDim.x + threadIdx.x;
        const int stride = (gridDim.x - PACK_BLOCKS) * blockDim.x;
        for (int i = base; i < TOT; i += stride) {
            int t  = i / (SQ * BH * (HD / 4));
            int r  = i - t * (SQ * BH * (HD / 4));
            int s  = r / (BH * (HD / 4));
            int r2 = r - s * (BH * (HD / 4));
            int bh = r2 >> 5;
            int c  = (r2 & 31) << 2;
            const float* src = (t == 0) ? Q : (t == 1) ? K : V;
            __half*      dst = (t == 0) ? g_qh : (t == 1) ? g_kh : g_vh;
            float4 v = *(const float4*)(src + (size_t)s * ROWSTRIDE + bh * HD + c);
            if (t == 0) { v.x *= SCL2; v.y *= SCL2; v.z *= SCL2; v.w *= SCL2; }
            __half2 h0 = __floats2half2_rn(v.x, v.y);
            __half2 h1 = __floats2half2_rn(v.z, v.w);
            uint2 u; u.x = *(uint32_t*)&h0; u.y = *(uint32_t*)&h1;
            *(uint2*)(dst + ((size_t)bh * SQ + s) * HD + c) = u;
        }
    }
}

// ---------------- helpers ----------------
__device__ __forceinline__ uint32_t smem_u32(const void* p) {
    return (uint32_t)__cvta_generic_to_shared(p);
}
__device__ __forceinline__ void cp_async16(uint32_t dst, const void* src) {
    asm volatile("cp.async.cg.shared.global [%0], [%1], 16;" :: "r"(dst), "l"(src));
}
__device__ __forceinline__ void cp_commit() { asm volatile("cp.async.commit_group;"); }
template <int N> __device__ __forceinline__ void cp_wait() {
    asm volatile("cp.async.wait_group %0;" :: "n"(N));
}
__device__ __forceinline__ float ex2(float x) {
    float y; asm("ex2.approx.ftz.f32 %0, %1;" : "=f"(y) : "f"(x)); return y;
}
__device__ __forceinline__ void ldm_x4(uint32_t* r, uint32_t a) {
    asm volatile("ldmatrix.sync.aligned.m8n8.x4.shared.b16 {%0,%1,%2,%3}, [%4];"
                 : "=r"(r[0]), "=r"(r[1]), "=r"(r[2]), "=r"(r[3]) : "r"(a));
}
__device__ __forceinline__ void ldm_x4_t(uint32_t* r, uint32_t a) {
    asm volatile("ldmatrix.sync.aligned.m8n8.x4.trans.shared.b16 {%0,%1,%2,%3}, [%4];"
                 : "=r"(r[0]), "=r"(r[1]), "=r"(r[2]), "=r"(r[3]) : "r"(a));
}
__device__ __forceinline__ void mma16816(float* c, const uint32_t* a, uint32_t b0, uint32_t b1) {
    asm volatile("mma.sync.aligned.m16n8k16.row.col.f32.f16.f16.f32 "
                 "{%0,%1,%2,%3}, {%4,%5,%6,%7}, {%8,%9}, {%0,%1,%2,%3};"
                 : "+f"(c[0]), "+f"(c[1]), "+f"(c[2]), "+f"(c[3])
                 : "r"(a[0]), "r"(a[1]), "r"(a[2]), "r"(a[3]), "r"(b0), "r"(b1));
}
__device__ __forceinline__ uint32_t packh2(float x, float y) {
    __half2 h = __floats2half2_rn(x, y);
    return *(uint32_t*)&h;
}

// stage K,V tile (fp16, swizzled) via cp.async (128 threads)
__device__ __forceinline__ void stage_tiles(int tid, int kb, const __half* Kh, const __half* Vh,
                                            char* sKs, char* sVs) {
    #pragma unroll
    for (int j = 0; j < 8; j++) {
        int i = tid + j * NTHREADS;          // 0..1023
        int r = i >> 4, ck = i & 15;
        size_t so = (size_t)(kb + r) * HD + ck * 8;
        uint32_t off = SWOFF(r, ck);
        cp_async16(smem_u32(sKs + off), Kh + so);
        cp_async16(smem_u32(sVs + off), Vh + so);
    }
}

__global__ void __launch_bounds__(NTHREADS, 2)
attn_fwd_kernel(float* __restrict__ Og) {
    extern __shared__ char smem[];
    char* sQ = smem + OFF_Q;
    char* sK[3] = { smem + OFF_KV,        smem + OFF_KV + 2 * TILE, smem + OFF_KV + 4 * TILE };
    char* sV[3] = { smem + OFF_KV + TILE, smem + OFF_KV + 3 * TILE, smem + OFF_KV + 5 * TILE };

    const int tid  = threadIdx.x;
    const int lane = tid & 31;
    const int warp = tid >> 5;

    const int q0 = blockIdx.x * BM;
    const int bh = blockIdx.y;
    const int bb = bh >> 4;
    const __half* Qh = g_qh + (size_t)bh * SQ * HD;
    const __half* Kh = g_kh + (size_t)bh * SQ * HD;
    const __half* Vh = g_vh + (size_t)bh * SQ * HD;

    // ---- prologue: async Q (64 rows) + tile0 (group 0), tile1 (group 1) ----
    #pragma unroll
    for (int j = 0; j < 8; j++) {
        int i = tid + j * NTHREADS;          // 0..1023
        int r = i >> 4, ck = i & 15;
        cp_async16(smem_u32(sQ + SWOFF(r, ck)), Qh + (size_t)(q0 + r) * HD + ck * 8);
    }
    stage_tiles(tid, 0, Kh, Vh, sK[0], sV[0]);
    cp_commit();                          // group: Q + tile0
    stage_tiles(tid, BN, Kh, Vh, sK[1], sV[1]);
    cp_commit();                          // group: tile1

    const int g  = lane >> 2;
    const int tg = lane & 3;
    const int m0 = warp * 16;             // warps 0..3 -> rows 0..63

    // lane row indices for fragment loads
    const int arow = m0 + (lane & 7) + ((lane >> 3) & 1) * 8;
    const int ach  = (lane >> 4);         // acol/8: 0 or 1
    const int krow = (lane & 7) + ((lane >> 4) & 1) * 8;
    const int kch  = (lane >> 3) & 1;     // kcol/8
    const int vrow = (lane & 7) + ((lane >> 3) & 1) * 8;
    const int vch  = (lane >> 4);         // vcol/8

    const uint8_t* mrow0 = (const uint8_t*)g_mp
                         + ((size_t)bb * SQ + q0 + m0 + g) * MROWB;
    const uint8_t* mrow1 = mrow0 + (size_t)8 * MROWB;
    const int msh = 2 * tg;

    float o[16][4];
    #pragma unroll
    for (int t = 0; t < 16; t++) { o[t][0]=0.f; o[t][1]=0.f; o[t][2]=0.f; o[t][3]=0.f; }
    float l0a = 0.f, l0b = 0.f, l1a = 0.f, l1b = 0.f;

    cp_wait<1>();          // Q + tile0 ready
    __syncthreads();
    uint32_t aq[8][4];
    #pragma unroll
    for (int kt = 0; kt < 8; kt++) {
        ldm_x4(aq[kt], smem_u32(sQ + SWOFF(arow, kt * 2 + ach)));
    }

    for (int it = 0; it < KVITERS; it++) {
        const int s = it % 3;
        char* sKs = sK[s];
        char* sVs = sV[s];

        // mask words for this tile (64 bits per row)
        uint2 w0 = *(const uint2*)(mrow0 + it * 8);
        uint2 w1 = *(const uint2*)(mrow1 + it * 8);
        const uint32_t wa0 = w0.x >> msh, wb0 = w0.y >> msh;
        const uint32_t wa1 = w1.x >> msh, wb1 = w1.y >> msh;

        cp_wait<1>();          // tile it arrived (committed 2 groups back)
        __syncthreads();       // visibility + WAR separation (single barrier per iter)

        // stage tile it+2 into buffer (it+2)%3 (last read in iter it-1; safe after sync)
        if (it + 2 < KVITERS) {
            stage_tiles(tid, (it + 2) * BN, Kh, Vh, sK[(it + 2) % 3], sV[(it + 2) % 3]);
        }
        cp_commit();

        // ---- S = Q @ K^T, kt-outer, explicit B-fragment double buffering ----
        float c4[8][4];
        #pragma unroll
        for (int t = 0; t < 8; t++) { c4[t][0]=0.f; c4[t][1]=0.f; c4[t][2]=0.f; c4[t][3]=0.f; }
        {
            uint32_t bq[2][4];
            ldm_x4(bq[0], smem_u32(sKs + SWOFF(krow, kch)));     // kt=0, n16=0
            #pragma unroll
            for (int idx = 0; idx < 32; idx++) {
                const int kt  = idx >> 2;
                const int n16 = idx & 3;
                if (idx + 1 < 32) {
                    const int kt2 = (idx + 1) >> 2;
                    const int n2  = (idx + 1) & 3;
                    ldm_x4(bq[(idx + 1) & 1],
                           smem_u32(sKs + SWOFF(n2 * 16 + krow, kt2 * 2 + kch)));
                }
                const uint32_t* b = bq[idx & 1];
                mma16816(c4[2 * n16],     aq[kt], b[0], b[1]);
                mma16816(c4[2 * n16 + 1], aq[kt], b[2], b[3]);
            }
        }

        // ---- mask + exp2 + pack ----
        uint32_t pf[4][4];
        #pragma unroll
        for (int nt = 0; nt < 8; nt++) {
            uint32_t ba  = (nt < 4) ? (wa0 >> (8 * nt)) : (wb0 >> (8 * (nt - 4)));
            uint32_t bb_ = (nt < 4) ? (wa1 >> (8 * nt)) : (wb1 >> (8 * (nt - 4)));
            float x0 = (ba  & 1u) ? -200.f : c4[nt][0];
            float x1 = (ba  & 2u) ? -200.f : c4[nt][1];
            float x2 = (bb_ & 1u) ? -200.f : c4[nt][2];
            float x3 = (bb_ & 2u) ? -200.f : c4[nt][3];
            float p0 = ex2(x0), p1 = ex2(x1), p2 = ex2(x2), p3 = ex2(x3);
            l0a += p0; l0b += p1;
            l1a += p2; l1b += p3;
            pf[nt >> 1][(nt & 1) * 2]     = packh2(p0, p1);
            pf[nt >> 1][(nt & 1) * 2 + 1] = packh2(p2, p3);
        }

        // ---- O += P @ V, j-outer, explicit V-fragment double buffering ----
        {
            uint32_t bv[2][4];
            ldm_x4_t(bv[0], smem_u32(sVs + SWOFF(vrow, vch)));   // j=0, dn=0
            #pragma unroll
            for (int idx = 0; idx < 32; idx++) {
                const int j  = idx >> 3;
                const int dn = idx & 7;
                if (idx + 1 < 32) {
                    const int j2  = (idx + 1) >> 3;
                    const int dn2 = (idx + 1) & 7;
                    ldm_x4_t(bv[(idx + 1) & 1],
                             smem_u32(sVs + SWOFF(j2 * 16 + vrow, dn2 * 2 + vch)));
                }
                const uint32_t* v = bv[idx & 1];
                mma16816(o[2 * dn],     pf[j], v[0], v[1]);
                mma16816(o[2 * dn + 1], pf[j], v[2], v[3]);
            }
        }
    }

    // ---- epilogue: quad-reduce l, normalize, store ----
    float l0 = l0a + l0b;
    float l1 = l1a + l1b;
    l0 += __shfl_xor_sync(0xffffffffu, l0, 1);
    l0 += __shfl_xor_sync(0xffffffffu, l0, 2);
    l1 += __shfl_xor_sync(0xffffffffu, l1, 1);
    l1 += __shfl_xor_sync(0xffffffffu, l1, 2);
    float i0 = 1.f / l0;
    float i1 = 1.f / l1;

    float* orow0 = Og + (size_t)(q0 + m0 + g) * ROWSTRIDE + bh * HD;
    float* orow1 = orow0 + (size_t)8 * ROWSTRIDE;
    #pragma unroll
    for (int nt = 0; nt < 16; nt++) {
        float2 v0, v1;
        v0.x = o[nt][0] * i0; v0.y = o[nt][1] * i0;
        v1.x = o[nt][2] * i1; v1.y = o[nt][3] * i1;
        *(float2*)(orow0 + nt * 8 + 2 * tg) = v0;
        *(float2*)(orow1 + nt * 8 + 2 * tg) = v1;
    }
}

extern "C" void kernel_launch(void* const* d_in, const int* in_sizes, int n_in,
                              void* d_out, int out_size) {
    const float* Q = (const float*)d_in[0];
    const float* K = (const float*)d_in[1];
    const float* V = (const float*)d_in[2];
    const void*  M = d_in[3];
    float*       O = (float*)d_out;

    detect_kernel<<<256, 256>>>((const uint32_t*)M);
    prep_kernel<<<PACK_BLOCKS + 8192, 256>>>(M, Q, K, V);

    cudaFuncSetAttribute(attn_fwd_kernel, cudaFuncAttributeMaxDynamicSharedMemorySize, SMEM_BYTES);
    dim3 grid(SQ / BM, BH);
    attn_fwd_kernel<<<grid, NTHREADS, SMEM_BYTES>>>(O);
}

// round 15
// speedup vs baseline: 1.6343x; 1.0055x over previous
#include <cuda_runtime.h>
#include <cuda_fp16.h>
#include <cstdint>

// ---------------- problem constants ----------------
#define SQ   2048
#define NB   2
#define NH   16
#define BH   (NB * NH)             // 32
#define HD   128
#define ROWSTRIDE (BH * HD)        // 4096 floats
#define MASK_ELEMS (NB * SQ * SQ)  // 8388608
#define MROWB (SQ / 8)             // 256 bytes per packed mask row

// ---------------- tiling ----------------
#define BM        64               // q rows per CTA (4 warps x 16)
#define BN        64
#define NTHREADS  128
#define KVITERS   (SQ / BN)        // 32

#define SCALE  0.08838834764831845f       // 1/sqrt(128)
#define LOG2E  1.4426950408889634f
#define SCL2   (SCALE * LOG2E)            // folded into Q in prepass

// smem per CTA (swizzled, 256B rows, no padding):
//   Q (16K) | K0 V0 K1 V1 K2 V2 (6 x 16K)  = 114688 B -> 2 CTAs/SM
#define TILE    16384
#define OFF_Q   0
#define OFF_KV  16384
#define SMEM_BYTES (OFF_Q + 7 * TILE)   // 114688

// swizzled byte offset of 16B chunk ck (0..15) in row r (256B rows)
#define SWOFF(r, ck) (((r) << 8) + ((((ck) ^ ((r) & 7))) << 4))

// ---------------- global scratch ----------------
__device__ __half   g_qh[(size_t)BH * SQ * HD];   // Q prescaled by SCL2
__device__ __half   g_kh[(size_t)BH * SQ * HD];
__device__ __half   g_vh[(size_t)BH * SQ * HD];
__device__ uint32_t g_mp[MASK_ELEMS / 32];        // packed mask bits
__device__ int      g_flags[2] = {0, 0};          // static init; detect only ORs (idempotent)

// sample-based dtype detect: scan first 1MB (262144 words).
__global__ void detect_kernel(const uint32_t* __restrict__ m) {
    int f_f32 = 0, f_u8 = 0;
    int i = blockIdx.x * blockDim.x + threadIdx.x;    // 65536 threads x 4 words
    #pragma unroll
    for (int j = 0; j < 4; j++) {
        uint32_t w = m[i + j * 65536];
        if (w == 0x3F800000u) f_f32 = 1;
        else if (w > 1u)      f_u8  = 1;
    }
    if (f_f32) atomicOr(&g_flags[0], 1);
    if (f_u8)  atomicOr(&g_flags[1], 1);
}

// fused prep: blocks [0,1024) pack mask bits; blocks [1024,9216) convert QKV
#define PACK_BLOCKS 1024
__global__ void prep_kernel(const void* __restrict__ m,
                            const float* __restrict__ Q, const float* __restrict__ K,
                            const float* __restrict__ V) {
    if (blockIdx.x < PACK_BLOCKS) {
        const int u8mode = (!g_flags[0] && g_flags[1]);
        const int w = blockIdx.x * blockDim.x + threadIdx.x;   // exactly MASK_ELEMS/32 threads
        uint32_t bits = 0;
        if (u8mode) {
            const uint8_t* p = (const uint8_t*)m + (size_t)w * 32;
            #pragma unroll
            for (int j = 0; j < 32; j++) bits |= (uint32_t)(p[j] != 0) << j;
        } else {
            const uint32_t* p = (const uint32_t*)m + (size_t)w * 32;
            #pragma unroll
            for (int j = 0; j < 32; j++) bits |= (uint32_t)(p[j] != 0u) << j;
        }
        g_mp[w] = bits;
    } else {
        const int TOT = 3 * SQ * BH * (HD / 4);
        const int base = (blockIdx.x - PACK_BLOCKS) * blockDim.x + threadIdx.x;
        const int stride = (gridDim.x - PACK_BLOCKS) * blockDim.x;
        for (int i = base; i < TOT; i += stride) {
            int t  = i / (SQ * BH * (HD / 4));
            int r  = i - t * (SQ * BH * (HD / 4));
            int s  = r / (BH * (HD / 4));
            int r2 = r - s * (BH * (HD / 4));
            int bh = r2 >> 5;
            int c  = (r2 & 31) << 2;
            const float* src = (t == 0) ? Q : (t == 1) ? K : V;
            __half*      dst = (t == 0) ? g_qh : (t == 1) ? g_kh : g_vh;
            float4 v = *(const float4*)(src + (size_t)s * ROWSTRIDE + bh * HD + c);
            if (t == 0) { v.x *= SCL2; v.y *= SCL2; v.z *= SCL2; v.w *= SCL2; }
            __half2 h0 = __floats2half2_rn(v.x, v.y);
            __half2 h1 = __floats2half2_rn(v.z, v.w);
            uint2 u; u.x = *(uint32_t*)&h0; u.y = *(uint32_t*)&h1;
            *(uint2*)(dst + ((size_t)bh * SQ + s) * HD + c) = u;
        }
    }
}

// ---------------- helpers ----------------
__device__ __forceinline__ uint32_t smem_u32(const void* p) {
    return (uint32_t)__cvta_generic_to_shared(p);
}
__device__ __forceinline__ void cp_async16(uint32_t dst, const void* src) {
    asm volatile("cp.async.cg.shared.global [%0], [%1], 16;" :: "r"(dst), "l"(src));
}
__device__ __forceinline__ void cp_commit() { asm volatile("cp.async.commit_group;"); }
template <int N> __device__ __forceinline__ void cp_wait() {
    asm volatile("cp.async.wait_group %0;" :: "n"(N));
}
__device__ __forceinline__ float ex2(float x) {
    float y; asm("ex2.approx.ftz.f32 %0, %1;" : "=f"(y) : "f"(x)); return y;
}
__device__ __forceinline__ void ldm_x4(uint32_t* r, uint32_t a) {
    asm volatile("ldmatrix.sync.aligned.m8n8.x4.shared.b16 {%0,%1,%2,%3}, [%4];"
                 : "=r"(r[0]), "=r"(r[1]), "=r"(r[2]), "=r"(r[3]) : "r"(a));
}
__device__ __forceinline__ void ldm_x4_t(uint32_t* r, uint32_t a) {
    asm volatile("ldmatrix.sync.aligned.m8n8.x4.trans.shared.b16 {%0,%1,%2,%3}, [%4];"
                 : "=r"(r[0]), "=r"(r[1]), "=r"(r[2]), "=r"(r[3]) : "r"(a));
}
__device__ __forceinline__ void mma16816(float* c, const uint32_t* a, uint32_t b0, uint32_t b1) {
    asm volatile("mma.sync.aligned.m16n8k16.row.col.f32.f16.f16.f32 "
                 "{%0,%1,%2,%3}, {%4,%5,%6,%7}, {%8,%9}, {%0,%1,%2,%3};"
                 : "+f"(c[0]), "+f"(c[1]), "+f"(c[2]), "+f"(c[3])
                 : "r"(a[0]), "r"(a[1]), "r"(a[2]), "r"(a[3]), "r"(b0), "r"(b1));
}
__device__ __forceinline__ uint32_t packh2(float x, float y) {
    __half2 h = __floats2half2_rn(x, y);
    return *(uint32_t*)&h;
}

// stage K,V tile (fp16, swizzled) via cp.async (128 threads)
__device__ __forceinline__ void stage_tiles(int tid, int kb, const __half* Kh, const __half* Vh,
                                            char* sKs, char* sVs) {
    #pragma unroll
    for (int j = 0; j < 8; j++) {
        int i = tid + j * NTHREADS;          // 0..1023
        int r = i >> 4, ck = i & 15;
        size_t so = (size_t)(kb + r) * HD + ck * 8;
        uint32_t off = SWOFF(r, ck);
        cp_async16(smem_u32(sKs + off), Kh + so);
        cp_async16(smem_u32(sVs + off), Vh + so);
    }
}

__global__ void __launch_bounds__(NTHREADS, 2)
attn_fwd_kernel(float* __restrict__ Og) {
    extern __shared__ char smem[];
    char* sQ = smem + OFF_Q;
    char* sK[3] = { smem + OFF_KV,        smem + OFF_KV + 2 * TILE, smem + OFF_KV + 4 * TILE };
    char* sV[3] = { smem + OFF_KV + TILE, smem + OFF_KV + 3 * TILE, smem + OFF_KV + 5 * TILE };

    const int tid  = threadIdx.x;
    const int lane = tid & 31;
    const int warp = tid >> 5;

    const int q0 = blockIdx.x * BM;
    const int bh = blockIdx.y;
    const int bb = bh >> 4;
    const __half* Qh = g_qh + (size_t)bh * SQ * HD;
    const __half* Kh = g_kh + (size_t)bh * SQ * HD;
    const __half* Vh = g_vh + (size_t)bh * SQ * HD;

    // ---- prologue: async Q (64 rows) + tile0 (group 0), tile1 (group 1) ----
    #pragma unroll
    for (int j = 0; j < 8; j++) {
        int i = tid + j * NTHREADS;          // 0..1023
        int r = i >> 4, ck = i & 15;
        cp_async16(smem_u32(sQ + SWOFF(r, ck)), Qh + (size_t)(q0 + r) * HD + ck * 8);
    }
    stage_tiles(tid, 0, Kh, Vh, sK[0], sV[0]);
    cp_commit();                          // group: Q + tile0
    stage_tiles(tid, BN, Kh, Vh, sK[1], sV[1]);
    cp_commit();                          // group: tile1

    const int g  = lane >> 2;
    const int tg = lane & 3;
    const int m0 = warp * 16;             // warps 0..3 -> rows 0..63

    // lane row indices for fragment loads
    const int arow = m0 + (lane & 7) + ((lane >> 3) & 1) * 8;
    const int ach  = (lane >> 4);         // acol/8: 0 or 1
    const int krow = (lane & 7) + ((lane >> 4) & 1) * 8;
    const int kch  = (lane >> 3) & 1;     // kcol/8
    const int vrow = (lane & 7) + ((lane >> 3) & 1) * 8;
    const int vch  = (lane >> 4);         // vcol/8

    const uint8_t* mrow0 = (const uint8_t*)g_mp
                         + ((size_t)bb * SQ + q0 + m0 + g) * MROWB;
    const uint8_t* mrow1 = mrow0 + (size_t)8 * MROWB;
    const int msh = 2 * tg;

    float o[16][4];
    #pragma unroll
    for (int t = 0; t < 16; t++) { o[t][0]=0.f; o[t][1]=0.f; o[t][2]=0.f; o[t][3]=0.f; }
    float l0a = 0.f, l0b = 0.f, l1a = 0.f, l1b = 0.f;

    cp_wait<1>();          // Q + tile0 ready
    __syncthreads();
    uint32_t aq[8][4];
    #pragma unroll
    for (int kt = 0; kt < 8; kt++) {
        ldm_x4(aq[kt], smem_u32(sQ + SWOFF(arow, kt * 2 + ach)));
    }

    for (int it = 0; it < KVITERS; it++) {
        const int s = it % 3;
        char* sKs = sK[s];
        char* sVs = sV[s];

        // mask words for this tile (64 bits per row)
        uint2 w0 = *(const uint2*)(mrow0 + it * 8);
        uint2 w1 = *(const uint2*)(mrow1 + it * 8);
        const uint32_t wa0 = w0.x >> msh, wb0 = w0.y >> msh;
        const uint32_t wa1 = w1.x >> msh, wb1 = w1.y >> msh;

        cp_wait<1>();          // tile it arrived (committed 2 groups back)
        __syncthreads();       // visibility + WAR separation (single barrier per iter)

        // stage tile it+2 into buffer (it+2)%3 (last read in iter it-1; safe after sync)
        if (it + 2 < KVITERS) {
            stage_tiles(tid, (it + 2) * BN, Kh, Vh, sK[(it + 2) % 3], sV[(it + 2) % 3]);
        }
        cp_commit();

        // ---- S = Q @ K^T, kt-outer, B-fragment prefetch depth 2 ----
        float c4[8][4];
        #pragma unroll
        for (int t = 0; t < 8; t++) { c4[t][0]=0.f; c4[t][1]=0.f; c4[t][2]=0.f; c4[t][3]=0.f; }
        {
            uint32_t bq[3][4];
            ldm_x4(bq[0], smem_u32(sKs + SWOFF(krow, kch)));            // idx 0: kt0,n0
            ldm_x4(bq[1], smem_u32(sKs + SWOFF(16 + krow, kch)));       // idx 1: kt0,n1
            #pragma unroll
            for (int idx = 0; idx < 32; idx++) {
                const int kt  = idx >> 2;
                const int n16 = idx & 3;
                if (idx + 2 < 32) {
                    const int kt2 = (idx + 2) >> 2;
                    const int n2  = (idx + 2) & 3;
                    ldm_x4(bq[(idx + 2) % 3],
                           smem_u32(sKs + SWOFF(n2 * 16 + krow, kt2 * 2 + kch)));
                }
                const uint32_t* b = bq[idx % 3];
                mma16816(c4[2 * n16],     aq[kt], b[0], b[1]);
                mma16816(c4[2 * n16 + 1], aq[kt], b[2], b[3]);
            }
        }

        // ---- mask + exp2 + pack ----
        uint32_t pf[4][4];
        #pragma unroll
        for (int nt = 0; nt < 8; nt++) {
            uint32_t ba  = (nt < 4) ? (wa0 >> (8 * nt)) : (wb0 >> (8 * (nt - 4)));
            uint32_t bb_ = (nt < 4) ? (wa1 >> (8 * nt)) : (wb1 >> (8 * (nt - 4)));
            float x0 = (ba  & 1u) ? -200.f : c4[nt][0];
            float x1 = (ba  & 2u) ? -200.f : c4[nt][1];
            float x2 = (bb_ & 1u) ? -200.f : c4[nt][2];
            float x3 = (bb_ & 2u) ? -200.f : c4[nt][3];
            float p0 = ex2(x0), p1 = ex2(x1), p2 = ex2(x2), p3 = ex2(x3);
            l0a += p0; l0b += p1;
            l1a += p2; l1b += p3;
            pf[nt >> 1][(nt & 1) * 2]     = packh2(p0, p1);
            pf[nt >> 1][(nt & 1) * 2 + 1] = packh2(p2, p3);
        }

        // ---- O += P @ V, j-outer, V-fragment prefetch depth 2 ----
        {
            uint32_t bv[3][4];
            ldm_x4_t(bv[0], smem_u32(sVs + SWOFF(vrow, vch)));          // idx 0: j0,dn0
            ldm_x4_t(bv[1], smem_u32(sVs + SWOFF(vrow, 2 + vch)));      // idx 1: j0,dn1
            #pragma unroll
            for (int idx = 0; idx < 32; idx++) {
                const int j  = idx >> 3;
                const int dn = idx & 7;
                if (idx + 2 < 32) {
                    const int j2  = (idx + 2) >> 3;
                    const int dn2 = (idx + 2) & 7;
                    ldm_x4_t(bv[(idx + 2) % 3],
                             smem_u32(sVs + SWOFF(j2 * 16 + vrow, dn2 * 2 + vch)));
                }
                const uint32_t* v = bv[idx % 3];
                mma16816(o[2 * dn],     pf[j], v[0], v[1]);
                mma16816(o[2 * dn + 1], pf[j], v[2], v[3]);
            }
        }
    }

    // ---- epilogue: quad-reduce l, normalize, store ----
    float l0 = l0a + l0b;
    float l1 = l1a + l1b;
    l0 += __shfl_xor_sync(0xffffffffu, l0, 1);
    l0 += __shfl_xor_sync(0xffffffffu, l0, 2);
    l1 += __shfl_xor_sync(0xffffffffu, l1, 1);
    l1 += __shfl_xor_sync(0xffffffffu, l1, 2);
    float i0 = 1.f / l0;
    float i1 = 1.f / l1;

    float* orow0 = Og + (size_t)(q0 + m0 + g) * ROWSTRIDE + bh * HD;
    float* orow1 = orow0 + (size_t)8 * ROWSTRIDE;
    #pragma unroll
    for (int nt = 0; nt < 16; nt++) {
        float2 v0, v1;
        v0.x = o[nt][0] * i0; v0.y = o[nt][1] * i0;
        v1.x = o[nt][2] * i1; v1.y = o[nt][3] * i1;
        *(float2*)(orow0 + nt * 8 + 2 * tg) = v0;
        *(float2*)(orow1 + nt * 8 + 2 * tg) = v1;
    }
}

extern "C" void kernel_launch(void* const* d_in, const int* in_sizes, int n_in,
                              void* d_out, int out_size) {
    const float* Q = (const float*)d_in[0];
    const float* K = (const float*)d_in[1];
    const float* V = (const float*)d_in[2];
    const void*  M = d_in[3];
    float*       O = (float*)d_out;

    detect_kernel<<<256, 256>>>((const uint32_t*)M);
    prep_kernel<<<PACK_BLOCKS + 8192, 256>>>(M, Q, K, V);

    cudaFuncSetAttribute(attn_fwd_kernel, cudaFuncAttributeMaxDynamicSharedMemorySize, SMEM_BYTES);
    dim3 grid(SQ / BM, BH);
    attn_fwd_kernel<<<grid, NTHREADS, SMEM_BYTES>>>(O);
}

// round 16
// speedup vs baseline: 1.6581x; 1.0146x over previous
#include <cuda_runtime.h>
#include <cuda_fp16.h>
#include <cstdint>

// ---------------- problem constants ----------------
#define SQ   2048
#define NB   2
#define NH   16
#define BH   (NB * NH)             // 32
#define HD   128
#define ROWSTRIDE (BH * HD)        // 4096 floats
#define MASK_ELEMS (NB * SQ * SQ)  // 8388608
#define MROWB (SQ / 8)             // 256 bytes per packed mask row

// ---------------- tiling ----------------
#define BM        64               // q rows per CTA (4 warps x 16)
#define BN        64
#define NTHREADS  128
#define KVITERS   (SQ / BN)        // 32

#define SCALE  0.08838834764831845f       // 1/sqrt(128)
#define LOG2E  1.4426950408889634f
#define SCL2   (SCALE * LOG2E)            // folded into Q in prepass

// smem per CTA (swizzled, 256B rows, no padding):
//   Q (16K) | K0 V0 K1 V1 K2 V2 (6 x 16K)  = 114688 B -> 2 CTAs/SM
#define TILE    16384
#define OFF_Q   0
#define OFF_KV  16384
#define SMEM_BYTES (OFF_Q + 7 * TILE)   // 114688

// swizzled byte offset of 16B chunk ck (0..15) in row r (256B rows)
#define SWOFF(r, ck) (((r) << 8) + ((((ck) ^ ((r) & 7))) << 4))

// ---------------- global scratch ----------------
__device__ __half   g_qh[(size_t)BH * SQ * HD];   // Q prescaled by SCL2
__device__ __half   g_kh[(size_t)BH * SQ * HD];
__device__ __half   g_vh[(size_t)BH * SQ * HD];
__device__ uint32_t g_mp[MASK_ELEMS / 32];        // packed mask bits

// fused prep: blocks [0,1024) pack mask bits (self-detecting dtype);
//             blocks [1024,9216) convert QKV
#define PACK_BLOCKS 1024
__global__ void prep_kernel(const void* __restrict__ m,
                            const float* __restrict__ Q, const float* __restrict__ K,
                            const float* __restrict__ V) {
    if (blockIdx.x < PACK_BLOCKS) {
        // local dtype detect: sample first 512 words of the mask buffer.
        // u8-packed: P(no word>1 in 512 words) ~ 0.73^512 ~ 1e-70.
        // int32/f32 bool: words are 0/1 or 0/0x3F800000 -> no word in (1, 0x3F800000),
        // and f32 has w==0x3F800000 present.
        __shared__ int s_u8mode;
        if (threadIdx.x < 64) {
            const uint32_t* p = (const uint32_t*)m;
            int f_sig = 0;   // saw u8-packed signature (w>1 and != 1.0f bits)
            #pragma unroll
            for (int j = 0; j < 8; j++) {
                uint32_t w = p[threadIdx.x * 8 + j];
                if (w > 1u && w != 0x3F800000u) f_sig = 1;
            }
            if (threadIdx.x == 0) s_u8mode = 0;
            __syncwarp();
            if (f_sig) s_u8mode = 1;       // benign race: only writes 1
        }
        __syncthreads();
        const int u8mode = s_u8mode;

        const int w = blockIdx.x * blockDim.x + threadIdx.x;   // exactly MASK_ELEMS/32 threads
        uint32_t bits = 0;
        if (u8mode) {
            const uint8_t* p = (const uint8_t*)m + (size_t)w * 32;
            #pragma unroll
            for (int j = 0; j < 32; j++) bits |= (uint32_t)(p[j] != 0) << j;
        } else {
            const uint32_t* p = (const uint32_t*)m + (size_t)w * 32;
            #pragma unroll
            for (int j = 0; j < 32; j++) bits |= (uint32_t)(p[j] != 0u) << j;
        }
        g_mp[w] = bits;
    } else {
        const int TOT = 3 * SQ * BH * (HD / 4);
        const int base = (blockIdx.x - PACK_BLOCKS) * blockDim.x + threadIdx.x;
        const int stride = (gridDim.x - PACK_BLOCKS) * blockDim.x;
        for (int i = base; i < TOT; i += stride) {
            int t  = i / (SQ * BH * (HD / 4));
            int r  = i - t * (SQ * BH * (HD / 4));
            int s  = r / (BH * (HD / 4));
            int r2 = r - s * (BH * (HD / 4));
            int bh = r2 >> 5;
            int c  = (r2 & 31) << 2;
            const float* src = (t == 0) ? Q : (t == 1) ? K : V;
            __half*      dst = (t == 0) ? g_qh : (t == 1) ? g_kh : g_vh;
            float4 v = *(const float4*)(src + (size_t)s * ROWSTRIDE + bh * HD + c);
            if (t == 0) { v.x *= SCL2; v.y *= SCL2; v.z *= SCL2; v.w *= SCL2; }
            __half2 h0 = __floats2half2_rn(v.x, v.y);
            __half2 h1 = __floats2half2_rn(v.z, v.w);
            uint2 u; u.x = *(uint32_t*)&h0; u.y = *(uint32_t*)&h1;
            *(uint2*)(dst + ((size_t)bh * SQ + s) * HD + c) = u;
        }
    }
}

// ---------------- helpers ----------------
__device__ __forceinline__ uint32_t smem_u32(const void* p) {
    return (uint32_t)__cvta_generic_to_shared(p);
}
__device__ __forceinline__ void cp_async16(uint32_t dst, const void* src) {
    asm volatile("cp.async.cg.shared.global [%0], [%1], 16;" :: "r"(dst), "l"(src));
}
__device__ __forceinline__ void cp_commit() { asm volatile("cp.async.commit_group;"); }
template <int N> __device__ __forceinline__ void cp_wait() {
    asm volatile("cp.async.wait_group %0;" :: "n"(N));
}
__device__ __forceinline__ float ex2(float x) {
    float y; asm("ex2.approx.ftz.f32 %0, %1;" : "=f"(y) : "f"(x)); return y;
}
__device__ __forceinline__ void ldm_x4(uint32_t* r, uint32_t a) {
    asm volatile("ldmatrix.sync.aligned.m8n8.x4.shared.b16 {%0,%1,%2,%3}, [%4];"
                 : "=r"(r[0]), "=r"(r[1]), "=r"(r[2]), "=r"(r[3]) : "r"(a));
}
__device__ __forceinline__ void ldm_x4_t(uint32_t* r, uint32_t a) {
    asm volatile("ldmatrix.sync.aligned.m8n8.x4.trans.shared.b16 {%0,%1,%2,%3}, [%4];"
                 : "=r"(r[0]), "=r"(r[1]), "=r"(r[2]), "=r"(r[3]) : "r"(a));
}
__device__ __forceinline__ void mma16816(float* c, const uint32_t* a, uint32_t b0, uint32_t b1) {
    asm volatile("mma.sync.aligned.m16n8k16.row.col.f32.f16.f16.f32 "
                 "{%0,%1,%2,%3}, {%4,%5,%6,%7}, {%8,%9}, {%0,%1,%2,%3};"
                 : "+f"(c[0]), "+f"(c[1]), "+f"(c[2]), "+f"(c[3])
                 : "r"(a[0]), "r"(a[1]), "r"(a[2]), "r"(a[3]), "r"(b0), "r"(b1));
}
__device__ __forceinline__ uint32_t packh2(float x, float y) {
    __half2 h = __floats2half2_rn(x, y);
    return *(uint32_t*)&h;
}

// stage K,V tile (fp16, swizzled) via cp.async (128 threads)
__device__ __forceinline__ void stage_tiles(int tid, int kb, const __half* Kh, const __half* Vh,
                                            char* sKs, char* sVs) {
    #pragma unroll
    for (int j = 0; j < 8; j++) {
        int i = tid + j * NTHREADS;          // 0..1023
        int r = i >> 4, ck = i & 15;
        size_t so = (size_t)(kb + r) * HD + ck * 8;
        uint32_t off = SWOFF(r, ck);
        cp_async16(smem_u32(sKs + off), Kh + so);
        cp_async16(smem_u32(sVs + off), Vh + so);
    }
}

__global__ void __launch_bounds__(NTHREADS, 2)
attn_fwd_kernel(float* __restrict__ Og) {
    extern __shared__ char smem[];
    char* sQ = smem + OFF_Q;
    char* sK[3] = { smem + OFF_KV,        smem + OFF_KV + 2 * TILE, smem + OFF_KV + 4 * TILE };
    char* sV[3] = { smem + OFF_KV + TILE, smem + OFF_KV + 3 * TILE, smem + OFF_KV + 5 * TILE };

    const int tid  = threadIdx.x;
    const int lane = tid & 31;
    const int warp = tid >> 5;

    const int q0 = blockIdx.x * BM;
    const int bh = blockIdx.y;
    const int bb = bh >> 4;
    const __half* Qh = g_qh + (size_t)bh * SQ * HD;
    const __half* Kh = g_kh + (size_t)bh * SQ * HD;
    const __half* Vh = g_vh + (size_t)bh * SQ * HD;

    // ---- prologue: async Q (64 rows) + tile0 (group 0), tile1 (group 1) ----
    #pragma unroll
    for (int j = 0; j < 8; j++) {
        int i = tid + j * NTHREADS;          // 0..1023
        int r = i >> 4, ck = i & 15;
        cp_async16(smem_u32(sQ + SWOFF(r, ck)), Qh + (size_t)(q0 + r) * HD + ck * 8);
    }
    stage_tiles(tid, 0, Kh, Vh, sK[0], sV[0]);
    cp_commit();                          // group: Q + tile0
    stage_tiles(tid, BN, Kh, Vh, sK[1], sV[1]);
    cp_commit();                          // group: tile1

    const int g  = lane >> 2;
    const int tg = lane & 3;
    const int m0 = warp * 16;             // warps 0..3 -> rows 0..63

    // lane row indices for fragment loads
    const int arow = m0 + (lane & 7) + ((lane >> 3) & 1) * 8;
    const int ach  = (lane >> 4);         // acol/8: 0 or 1
    const int krow = (lane & 7) + ((lane >> 4) & 1) * 8;
    const int kch  = (lane >> 3) & 1;     // kcol/8
    const int vrow = (lane & 7) + ((lane >> 3) & 1) * 8;
    const int vch  = (lane >> 4);         // vcol/8

    const uint8_t* mrow0 = (const uint8_t*)g_mp
                         + ((size_t)bb * SQ + q0 + m0 + g) * MROWB;
    const uint8_t* mrow1 = mrow0 + (size_t)8 * MROWB;
    const int msh = 2 * tg;

    float o[16][4];
    #pragma unroll
    for (int t = 0; t < 16; t++) { o[t][0]=0.f; o[t][1]=0.f; o[t][2]=0.f; o[t][3]=0.f; }
    float l0a = 0.f, l0b = 0.f, l1a = 0.f, l1b = 0.f;

    cp_wait<1>();          // Q + tile0 ready
    __syncthreads();
    uint32_t aq[8][4];
    #pragma unroll
    for (int kt = 0; kt < 8; kt++) {
        ldm_x4(aq[kt], smem_u32(sQ + SWOFF(arow, kt * 2 + ach)));
    }

    for (int it = 0; it < KVITERS; it++) {
        const int s = it % 3;
        char* sKs = sK[s];
        char* sVs = sV[s];

        // mask words for this tile (64 bits per row)
        uint2 w0 = *(const uint2*)(mrow0 + it * 8);
        uint2 w1 = *(const uint2*)(mrow1 + it * 8);
        const uint32_t wa0 = w0.x >> msh, wb0 = w0.y >> msh;
        const uint32_t wa1 = w1.x >> msh, wb1 = w1.y >> msh;

        cp_wait<1>();          // tile it arrived (committed 2 groups back)
        __syncthreads();       // visibility + WAR separation (single barrier per iter)

        // stage tile it+2 into buffer (it+2)%3 (last read in iter it-1; safe after sync)
        if (it + 2 < KVITERS) {
            stage_tiles(tid, (it + 2) * BN, Kh, Vh, sK[(it + 2) % 3], sV[(it + 2) % 3]);
        }
        cp_commit();

        // ---- S = Q @ K^T, kt-outer, B-fragment prefetch depth 2 ----
        float c4[8][4];
        #pragma unroll
        for (int t = 0; t < 8; t++) { c4[t][0]=0.f; c4[t][1]=0.f; c4[t][2]=0.f; c4[t][3]=0.f; }
        {
            uint32_t bq[3][4];
            ldm_x4(bq[0], smem_u32(sKs + SWOFF(krow, kch)));            // idx 0: kt0,n0
            ldm_x4(bq[1], smem_u32(sKs + SWOFF(16 + krow, kch)));       // idx 1: kt0,n1
            #pragma unroll
            for (int idx = 0; idx < 32; idx++) {
                const int kt  = idx >> 2;
                const int n16 = idx & 3;
                if (idx + 2 < 32) {
                    const int kt2 = (idx + 2) >> 2;
                    const int n2  = (idx + 2) & 3;
                    ldm_x4(bq[(idx + 2) % 3],
                           smem_u32(sKs + SWOFF(n2 * 16 + krow, kt2 * 2 + kch)));
                }
                const uint32_t* b = bq[idx % 3];
                mma16816(c4[2 * n16],     aq[kt], b[0], b[1]);
                mma16816(c4[2 * n16 + 1], aq[kt], b[2], b[3]);
            }
        }

        // ---- mask + exp2 + pack ----
        uint32_t pf[4][4];
        #pragma unroll
        for (int nt = 0; nt < 8; nt++) {
            uint32_t ba  = (nt < 4) ? (wa0 >> (8 * nt)) : (wb0 >> (8 * (nt - 4)));
            uint32_t bb_ = (nt < 4) ? (wa1 >> (8 * nt)) : (wb1 >> (8 * (nt - 4)));
            float x0 = (ba  & 1u) ? -200.f : c4[nt][0];
            float x1 = (ba  & 2u) ? -200.f : c4[nt][1];
            float x2 = (bb_ & 1u) ? -200.f : c4[nt][2];
            float x3 = (bb_ & 2u) ? -200.f : c4[nt][3];
            float p0 = ex2(x0), p1 = ex2(x1), p2 = ex2(x2), p3 = ex2(x3);
            l0a += p0; l0b += p1;
            l1a += p2; l1b += p3;
            pf[nt >> 1][(nt & 1) * 2]     = packh2(p0, p1);
            pf[nt >> 1][(nt & 1) * 2 + 1] = packh2(p2, p3);
        }

        // ---- O += P @ V, j-outer, V-fragment prefetch depth 2 ----
        {
            uint32_t bv[3][4];
            ldm_x4_t(bv[0], smem_u32(sVs + SWOFF(vrow, vch)));          // idx 0: j0,dn0
            ldm_x4_t(bv[1], smem_u32(sVs + SWOFF(vrow, 2 + vch)));      // idx 1: j0,dn1
            #pragma unroll
            for (int idx = 0; idx < 32; idx++) {
                const int j  = idx >> 3;
                const int dn = idx & 7;
                if (idx + 2 < 32) {
                    const int j2  = (idx + 2) >> 3;
                    const int dn2 = (idx + 2) & 7;
                    ldm_x4_t(bv[(idx + 2) % 3],
                             smem_u32(sVs + SWOFF(j2 * 16 + vrow, dn2 * 2 + vch)));
                }
                const uint32_t* v = bv[idx % 3];
                mma16816(o[2 * dn],     pf[j], v[0], v[1]);
                mma16816(o[2 * dn + 1], pf[j], v[2], v[3]);
            }
        }
    }

    // ---- epilogue: quad-reduce l, normalize, store ----
    float l0 = l0a + l0b;
    float l1 = l1a + l1b;
    l0 += __shfl_xor_sync(0xffffffffu, l0, 1);
    l0 += __shfl_xor_sync(0xffffffffu, l0, 2);
    l1 += __shfl_xor_sync(0xffffffffu, l1, 1);
    l1 += __shfl_xor_sync(0xffffffffu, l1, 2);
    float i0 = 1.f / l0;
    float i1 = 1.f / l1;

    float* orow0 = Og + (size_t)(q0 + m0 + g) * ROWSTRIDE + bh * HD;
    float* orow1 = orow0 + (size_t)8 * ROWSTRIDE;
    #pragma unroll
    for (int nt = 0; nt < 16; nt++) {
        float2 v0, v1;
        v0.x = o[nt][0] * i0; v0.y = o[nt][1] * i0;
        v1.x = o[nt][2] * i1; v1.y = o[nt][3] * i1;
        *(float2*)(orow0 + nt * 8 + 2 * tg) = v0;
        *(float2*)(orow1 + nt * 8 + 2 * tg) = v1;
    }
}

extern "C" void kernel_launch(void* const* d_in, const int* in_sizes, int n_in,
                              void* d_out, int out_size) {
    const float* Q = (const float*)d_in[0];
    const float* K = (const float*)d_in[1];
    const float* V = (const float*)d_in[2];
    const void*  M = d_in[3];
    float*       O = (float*)d_out;

    prep_kernel<<<PACK_BLOCKS + 8192, 256>>>(M, Q, K, V);

    cudaFuncSetAttribute(attn_fwd_kernel, cudaFuncAttributeMaxDynamicSharedMemorySize, SMEM_BYTES);
    dim3 grid(SQ / BM, BH);
    attn_fwd_kernel<<<grid, NTHREADS, SMEM_BYTES>>>(O);
}

// round 17
// speedup vs baseline: 1.7720x; 1.0687x over previous
#include <cuda_runtime.h>
#include <cuda_fp16.h>
#include <cstdint>

// ---------------- problem constants ----------------
#define SQ   2048
#define NB   2
#define NH   16
#define BH   (NB * NH)             // 32
#define HD   128
#define ROWSTRIDE (BH * HD)        // 4096 floats
#define MASK_ELEMS (NB * SQ * SQ)  // 8388608
#define MROWB (SQ / 8)             // 256 bytes per packed mask row

// ---------------- tiling ----------------
#define BM        64               // q rows per CTA (4 warps x 16)
#define BN        64
#define NTHREADS  128
#define KVITERS   (SQ / BN)        // 32

#define SCALE  0.08838834764831845f       // 1/sqrt(128)
#define LOG2E  1.4426950408889634f
#define SCL2   (SCALE * LOG2E)            // folded into Q in prepass

// smem per CTA (swizzled, 256B rows, no padding):
//   Q (16K) | K0 V0 K1 V1 K2 V2 (6 x 16K)  = 114688 B -> 2 CTAs/SM
#define TILE    16384
#define OFF_Q   0
#define OFF_KV  16384
#define SMEM_BYTES (OFF_Q + 7 * TILE)   // 114688

// swizzled byte offset of 16B chunk ck (0..15) in row r (256B rows)
#define SWOFF(r, ck) (((r) << 8) + ((((ck) ^ ((r) & 7))) << 4))

// ---------------- global scratch ----------------
__device__ __half   g_qh[(size_t)BH * SQ * HD];   // Q prescaled by SCL2
__device__ __half   g_kh[(size_t)BH * SQ * HD];
__device__ __half   g_vh[(size_t)BH * SQ * HD];
__device__ uint32_t g_mp[MASK_ELEMS / 32];        // packed mask bits

// fused prep: blocks [0,1024) pack mask bits (self-detecting dtype);
//             blocks [1024,9216) convert QKV
#define PACK_BLOCKS 1024
__global__ void prep_kernel(const void* __restrict__ m,
                            const float* __restrict__ Q, const float* __restrict__ K,
                            const float* __restrict__ V) {
    if (blockIdx.x < PACK_BLOCKS) {
        // local dtype detect: sample first 512 words of the mask buffer.
        __shared__ int s_u8mode;
        if (threadIdx.x < 64) {
            const uint32_t* p = (const uint32_t*)m;
            int f_sig = 0;
            #pragma unroll
            for (int j = 0; j < 8; j++) {
                uint32_t w = p[threadIdx.x * 8 + j];
                if (w > 1u && w != 0x3F800000u) f_sig = 1;
            }
            if (threadIdx.x == 0) s_u8mode = 0;
            __syncwarp();
            if (f_sig) s_u8mode = 1;       // benign race: only writes 1
        }
        __syncthreads();
        const int u8mode = s_u8mode;

        const int w = blockIdx.x * blockDim.x + threadIdx.x;
        uint32_t bits = 0;
        if (u8mode) {
            const uint8_t* p = (const uint8_t*)m + (size_t)w * 32;
            #pragma unroll
            for (int j = 0; j < 32; j++) bits |= (uint32_t)(p[j] != 0) << j;
        } else {
            const uint32_t* p = (const uint32_t*)m + (size_t)w * 32;
            #pragma unroll
            for (int j = 0; j < 32; j++) bits |= (uint32_t)(p[j] != 0u) << j;
        }
        g_mp[w] = bits;
    } else {
        const int TOT = 3 * SQ * BH * (HD / 4);
        const int base = (blockIdx.x - PACK_BLOCKS) * blockDim.x + threadIdx.x;
        const int stride = (gridDim.x - PACK_BLOCKS) * blockDim.x;
        for (int i = base; i < TOT; i += stride) {
            int t  = i / (SQ * BH * (HD / 4));
            int r  = i - t * (SQ * BH * (HD / 4));
            int s  = r / (BH * (HD / 4));
            int r2 = r - s * (BH * (HD / 4));
            int bh = r2 >> 5;
            int c  = (r2 & 31) << 2;
            const float* src = (t == 0) ? Q : (t == 1) ? K : V;
            __half*      dst = (t == 0) ? g_qh : (t == 1) ? g_kh : g_vh;
            float4 v = *(const float4*)(src + (size_t)s * ROWSTRIDE + bh * HD + c);
            if (t == 0) { v.x *= SCL2; v.y *= SCL2; v.z *= SCL2; v.w *= SCL2; }
            __half2 h0 = __floats2half2_rn(v.x, v.y);
            __half2 h1 = __floats2half2_rn(v.z, v.w);
            uint2 u; u.x = *(uint32_t*)&h0; u.y = *(uint32_t*)&h1;
            *(uint2*)(dst + ((size_t)bh * SQ + s) * HD + c) = u;
        }
    }
}

// ---------------- helpers ----------------
__device__ __forceinline__ uint32_t smem_u32(const void* p) {
    return (uint32_t)__cvta_generic_to_shared(p);
}
__device__ __forceinline__ void cp_async16(uint32_t dst, const void* src) {
    asm volatile("cp.async.cg.shared.global [%0], [%1], 16;" :: "r"(dst), "l"(src));
}
__device__ __forceinline__ void cp_commit() { asm volatile("cp.async.commit_group;"); }
template <int N> __device__ __forceinline__ void cp_wait() {
    asm volatile("cp.async.wait_group %0;" :: "n"(N));
}
__device__ __forceinline__ float ex2(float x) {
    float y; asm("ex2.approx.ftz.f32 %0, %1;" : "=f"(y) : "f"(x)); return y;
}
__device__ __forceinline__ void ldm_x4(uint32_t* r, uint32_t a) {
    asm volatile("ldmatrix.sync.aligned.m8n8.x4.shared.b16 {%0,%1,%2,%3}, [%4];"
                 : "=r"(r[0]), "=r"(r[1]), "=r"(r[2]), "=r"(r[3]) : "r"(a));
}
__device__ __forceinline__ void ldm_x4_t(uint32_t* r, uint32_t a) {
    asm volatile("ldmatrix.sync.aligned.m8n8.x4.trans.shared.b16 {%0,%1,%2,%3}, [%4];"
                 : "=r"(r[0]), "=r"(r[1]), "=r"(r[2]), "=r"(r[3]) : "r"(a));
}
__device__ __forceinline__ void mma16816(float* c, const uint32_t* a, uint32_t b0, uint32_t b1) {
    asm volatile("mma.sync.aligned.m16n8k16.row.col.f32.f16.f16.f32 "
                 "{%0,%1,%2,%3}, {%4,%5,%6,%7}, {%8,%9}, {%0,%1,%2,%3};"
                 : "+f"(c[0]), "+f"(c[1]), "+f"(c[2]), "+f"(c[3])
                 : "r"(a[0]), "r"(a[1]), "r"(a[2]), "r"(a[3]), "r"(b0), "r"(b1));
}
__device__ __forceinline__ uint32_t packh2(float x, float y) {
    __half2 h = __floats2half2_rn(x, y);
    return *(uint32_t*)&h;
}

// stage K,V tile (fp16, swizzled) via cp.async (128 threads)
__device__ __forceinline__ void stage_tiles(int tid, int kb, const __half* Kh, const __half* Vh,
                                            char* sKs, char* sVs) {
    #pragma unroll
    for (int j = 0; j < 8; j++) {
        int i = tid + j * NTHREADS;          // 0..1023
        int r = i >> 4, ck = i & 15;
        size_t so = (size_t)(kb + r) * HD + ck * 8;
        uint32_t off = SWOFF(r, ck);
        cp_async16(smem_u32(sKs + off), Kh + so);
        cp_async16(smem_u32(sVs + off), Vh + so);
    }
}

__global__ void __launch_bounds__(NTHREADS, 2)
attn_fwd_kernel(float* __restrict__ Og) {
    extern __shared__ char smem[];
    char* sQ = smem + OFF_Q;
    char* sK[3] = { smem + OFF_KV,        smem + OFF_KV + 2 * TILE, smem + OFF_KV + 4 * TILE };
    char* sV[3] = { smem + OFF_KV + TILE, smem + OFF_KV + 3 * TILE, smem + OFF_KV + 5 * TILE };

    const int tid  = threadIdx.x;
    const int lane = tid & 31;
    const int warp = tid >> 5;

    const int q0 = blockIdx.x * BM;
    const int bh = blockIdx.y;
    const int bb = bh >> 4;
    const __half* Qh = g_qh + (size_t)bh * SQ * HD;
    const __half* Kh = g_kh + (size_t)bh * SQ * HD;
    const __half* Vh = g_vh + (size_t)bh * SQ * HD;

    // ---- prologue: async Q (64 rows) + tile0 (group 0), tile1 (group 1) ----
    #pragma unroll
    for (int j = 0; j < 8; j++) {
        int i = tid + j * NTHREADS;          // 0..1023
        int r = i >> 4, ck = i & 15;
        cp_async16(smem_u32(sQ + SWOFF(r, ck)), Qh + (size_t)(q0 + r) * HD + ck * 8);
    }
    stage_tiles(tid, 0, Kh, Vh, sK[0], sV[0]);
    cp_commit();                          // group: Q + tile0
    stage_tiles(tid, BN, Kh, Vh, sK[1], sV[1]);
    cp_commit();                          // group: tile1

    const int g  = lane >> 2;
    const int tg = lane & 3;
    const int m0 = warp * 16;             // warps 0..3 -> rows 0..63

    // lane row indices for fragment loads
    const int arow = m0 + (lane & 7) + ((lane >> 3) & 1) * 8;
    const int ach  = (lane >> 4);         // acol/8: 0 or 1
    const int krow = (lane & 7) + ((lane >> 4) & 1) * 8;
    const int kch  = (lane >> 3) & 1;     // kcol/8
    const int vrow = (lane & 7) + ((lane >> 3) & 1) * 8;
    const int vch  = (lane >> 4);         // vcol/8

    const uint8_t* mrow0 = (const uint8_t*)g_mp
                         + ((size_t)bb * SQ + q0 + m0 + g) * MROWB;
    const uint8_t* mrow1 = mrow0 + (size_t)8 * MROWB;
    const int msh = 2 * tg;

    float o[16][4];
    #pragma unroll
    for (int t = 0; t < 16; t++) { o[t][0]=0.f; o[t][1]=0.f; o[t][2]=0.f; o[t][3]=0.f; }
    float l0a = 0.f, l0b = 0.f, l1a = 0.f, l1b = 0.f;

    cp_wait<1>();          // Q + tile0 ready
    __syncthreads();
    uint32_t aq[8][4];
    #pragma unroll
    for (int kt = 0; kt < 8; kt++) {
        ldm_x4(aq[kt], smem_u32(sQ + SWOFF(arow, kt * 2 + ach)));
    }

    for (int it = 0; it < KVITERS; it++) {
        const int s = it % 3;
        char* sKs = sK[s];
        char* sVs = sV[s];

        // mask words for this tile (64 bits per row)
        uint2 w0 = *(const uint2*)(mrow0 + it * 8);
        uint2 w1 = *(const uint2*)(mrow1 + it * 8);
        const uint32_t wa0 = w0.x >> msh, wb0 = w0.y >> msh;
        const uint32_t wa1 = w1.x >> msh, wb1 = w1.y >> msh;

        cp_wait<1>();          // tile it arrived (committed 2 groups back)
        __syncthreads();       // all warps past iter it-1: slot (it+2)%3 free, tile it visible

        // ---- S = Q @ K^T, kt-outer, B-fragment prefetch depth 2 ----
        float c4[8][4];
        #pragma unroll
        for (int t = 0; t < 8; t++) { c4[t][0]=0.f; c4[t][1]=0.f; c4[t][2]=0.f; c4[t][3]=0.f; }
        {
            uint32_t bq[3][4];
            ldm_x4(bq[0], smem_u32(sKs + SWOFF(krow, kch)));            // idx 0: kt0,n0
            ldm_x4(bq[1], smem_u32(sKs + SWOFF(16 + krow, kch)));       // idx 1: kt0,n1
            #pragma unroll
            for (int idx = 0; idx < 32; idx++) {
                const int kt  = idx >> 2;
                const int n16 = idx & 3;
                if (idx + 2 < 32) {
                    const int kt2 = (idx + 2) >> 2;
                    const int n2  = (idx + 2) & 3;
                    ldm_x4(bq[(idx + 2) % 3],
                           smem_u32(sKs + SWOFF(n2 * 16 + krow, kt2 * 2 + kch)));
                }
                const uint32_t* b = bq[idx % 3];
                mma16816(c4[2 * n16],     aq[kt], b[0], b[1]);
                mma16816(c4[2 * n16 + 1], aq[kt], b[2], b[3]);
            }
        }

        // ---- stage tile it+2 HERE: cp.async smem-writes flow through the
        //      crossbar during the softmax (MUFU/ALU) window instead of
        //      colliding with the QK/PV LDSM bursts ----
        if (it + 2 < KVITERS) {
            stage_tiles(tid, (it + 2) * BN, Kh, Vh, sK[(it + 2) % 3], sV[(it + 2) % 3]);
        }
        cp_commit();

        // ---- mask + exp2 + pack ----
        uint32_t pf[4][4];
        #pragma unroll
        for (int nt = 0; nt < 8; nt++) {
            uint32_t ba  = (nt < 4) ? (wa0 >> (8 * nt)) : (wb0 >> (8 * (nt - 4)));
            uint32_t bb_ = (nt < 4) ? (wa1 >> (8 * nt)) : (wb1 >> (8 * (nt - 4)));
            float x0 = (ba  & 1u) ? -200.f : c4[nt][0];
            float x1 = (ba  & 2u) ? -200.f : c4[nt][1];
            float x2 = (bb_ & 1u) ? -200.f : c4[nt][2];
            float x3 = (bb_ & 2u) ? -200.f : c4[nt][3];
            float p0 = ex2(x0), p1 = ex2(x1), p2 = ex2(x2), p3 = ex2(x3);
            l0a += p0; l0b += p1;
            l1a += p2; l1b += p3;
            pf[nt >> 1][(nt & 1) * 2]     = packh2(p0, p1);
            pf[nt >> 1][(nt & 1) * 2 + 1] = packh2(p2, p3);
        }

        // ---- O += P @ V, j-outer, V-fragment prefetch depth 2 ----
        {
            uint32_t bv[3][4];
            ldm_x4_t(bv[0], smem_u32(sVs + SWOFF(vrow, vch)));          // idx 0: j0,dn0
            ldm_x4_t(bv[1], smem_u32(sVs + SWOFF(vrow, 2 + vch)));      // idx 1: j0,dn1
            #pragma unroll
            for (int idx = 0; idx < 32; idx++) {
                const int j  = idx >> 3;
                const int dn = idx & 7;
                if (idx + 2 < 32) {
                    const int j2  = (idx + 2) >> 3;
                    const int dn2 = (idx + 2) & 7;
                    ldm_x4_t(bv[(idx + 2) % 3],
                             smem_u32(sVs + SWOFF(j2 * 16 + vrow, dn2 * 2 + vch)));
                }
                const uint32_t* v = bv[idx % 3];
                mma16816(o[2 * dn],     pf[j], v[0], v[1]);
                mma16816(o[2 * dn + 1], pf[j], v[2], v[3]);
            }
        }
    }

    // ---- epilogue: quad-reduce l, normalize, store ----
    float l0 = l0a + l0b;
    float l1 = l1a + l1b;
    l0 += __shfl_xor_sync(0xffffffffu, l0, 1);
    l0 += __shfl_xor_sync(0xffffffffu, l0, 2);
    l1 += __shfl_xor_sync(0xffffffffu, l1, 1);
    l1 += __shfl_xor_sync(0xffffffffu, l1, 2);
    float i0 = 1.f / l0;
    float i1 = 1.f / l1;

    float* orow0 = Og + (size_t)(q0 + m0 + g) * ROWSTRIDE + bh * HD;
    float* orow1 = orow0 + (size_t)8 * ROWSTRIDE;
    #pragma unroll
    for (int nt = 0; nt < 16; nt++) {
        float2 v0, v1;
        v0.x = o[nt][0] * i0; v0.y = o[nt][1] * i0;
        v1.x = o[nt][2] * i1; v1.y = o[nt][3] * i1;
        *(float2*)(orow0 + nt * 8 + 2 * tg) = v0;
        *(float2*)(orow1 + nt * 8 + 2 * tg) = v1;
    }
}

extern "C" void kernel_launch(void* const* d_in, const int* in_sizes, int n_in,
                              void* d_out, int out_size) {
    const float* Q = (const float*)d_in[0];
    const float* K = (const float*)d_in[1];
    const float* V = (const float*)d_in[2];
    const void*  M = d_in[3];
    float*       O = (float*)d_out;

    prep_kernel<<<PACK_BLOCKS + 8192, 256>>>(M, Q, K, V);

    cudaFuncSetAttribute(attn_fwd_kernel, cudaFuncAttributeMaxDynamicSharedMemorySize, SMEM_BYTES);
    dim3 grid(SQ / BM, BH);
    attn_fwd_kernel<<<grid, NTHREADS, SMEM_BYTES>>>(O);
}